// round 13
// baseline (speedup 1.0000x reference)
#include <cuda_runtime.h>
#include <cuda_fp16.h>
#include <math.h>
#include <stdint.h>

#define B_  4
#define L_  512
#define DS  128
#define DF  1000
#define H_  4
#define V_  32000
#define BL  2048    /* B*L   */
#define BHL 8192    /* B*H*L */

typedef __half f16;

// ---------------- fp32 scratch -------------------------------------------
__device__ float g_mu   [BL * DS];
__device__ float g_iv   [BL * DS];
__device__ float g_mu2  [BL];
__device__ float g_alpha[BL];
__device__ float g_mahal[(size_t)BHL * L_];
__device__ float g_xbuf [(size_t)BL * 2 * DF];
__device__ float g_part [4 * BL * DS];          // split-K partials for mu GEMM

// ---------------- fp16 hi/lo scratch ---------------------------------------
__device__ f16 g_muh[BL * DS],        g_mul[BL * DS];
__device__ f16 g_ivh[BL * 2 * DS],    g_ivl[BL * 2 * DS];
__device__ f16 g_qeh[BHL * 2 * DS],   g_qel[BHL * 2 * DS];
__device__ f16 g_wh [(size_t)BHL * L_],      g_wl [(size_t)BHL * L_];
__device__ f16 g_fth[(size_t)B_ * DF * L_];               // hi only (2-term B)
__device__ f16 g_mhh[(size_t)BL * H_ * DF],  g_mhl[(size_t)BL * H_ * DF];
__device__ f16 g_xh [(size_t)BL * 2 * DF],   g_xl [(size_t)BL * 2 * DF];
__device__ f16 g_hh [(size_t)BL * 2 * DF],   g_hl [(size_t)BL * 2 * DF];
__device__ f16 g_h1h[(size_t)BL * 4 * DF],   g_h1l[(size_t)BL * 4 * DF];
// weights (all single-rounded fp16)
__device__ f16 g_wqh[512 * DS];
__device__ f16 g_whdh[(size_t)DF * H_ * DF];
__device__ f16 g_wmuh[(size_t)2 * DS * 2 * DF];
__device__ f16 g_w1h[(size_t)2 * 4 * DF * 2 * DF];
__device__ f16 g_w2h[(size_t)2 * DF * 4 * DF];
__device__ f16 g_wlmh[(size_t)V_ * DF];

// ---------------- helpers --------------------------------------------------
__device__ __forceinline__ float warpSum(float v) {
    #pragma unroll
    for (int o = 16; o > 0; o >>= 1) v += __shfl_down_sync(0xffffffffu, v, o);
    return v;
}
__device__ float blockSum(float v, float* red) {
    int lane = threadIdx.x & 31, w = threadIdx.x >> 5;
    v = warpSum(v);
    __syncthreads();
    if (lane == 0) red[w] = v;
    __syncthreads();
    if (w == 0) {
        int nw = (blockDim.x + 31) >> 5;
        float t = (lane < nw) ? red[lane] : 0.f;
        t = warpSum(t);
        if (lane == 0) red[0] = t;
    }
    __syncthreads();
    return red[0];
}
__device__ __forceinline__ void split2(float v, f16* ph, f16* pl) {
    f16 h = __float2half_rn(v);
    *ph = h;
    *pl = __float2half_rn(v - __half2float(h));
}

// ---------------- mma.sync GEMM engine -------------------------------------
__device__ __forceinline__ void ldsm4(uint32_t& r0, uint32_t& r1, uint32_t& r2,
                                      uint32_t& r3, uint32_t a) {
    asm volatile("ldmatrix.sync.aligned.m8n8.x4.shared.b16 {%0,%1,%2,%3}, [%4];"
                 : "=r"(r0), "=r"(r1), "=r"(r2), "=r"(r3) : "r"(a));
}
__device__ __forceinline__ void mma_f16(float* c, const uint32_t* a,
                                        uint32_t b0, uint32_t b1) {
    asm volatile(
        "mma.sync.aligned.m16n8k16.row.col.f32.f16.f16.f32 "
        "{%0,%1,%2,%3}, {%4,%5,%6,%7}, {%8,%9}, {%0,%1,%2,%3};"
        : "+f"(c[0]), "+f"(c[1]), "+f"(c[2]), "+f"(c[3])
        : "r"(a[0]), "r"(a[1]), "r"(a[2]), "r"(a[3]), "r"(b0), "r"(b1));
}
__device__ __forceinline__ void cpa16(uint32_t dst, const void* src, bool p) {
    asm volatile("cp.async.cg.shared.global [%0], [%1], 16, %2;"
                 :: "r"(dst), "l"(src), "r"(p ? 16 : 0));
}
__device__ __forceinline__ void cpa_commit() {
    asm volatile("cp.async.commit_group;");
}
template<int NN>
__device__ __forceinline__ void cpa_wait() {
    asm volatile("cp.async.wait_group %0;" :: "n"(NN));
}

// EPI: 0 C=v; 1 C=v+bias; 3 split-out gelu(v+bias);
//      4 Cf=C+v+bias, also split Cf -> Ch/Cl; 5 split-out v;
//      6 C=v+bias, also split -> Ch/Cl;
//      7 qe-pack: Ch/Cl get split(q^2) at [orow,d] and split(-2q) at [orow,128+d]
template<int EPI>
__device__ __forceinline__ void epi_store(float v, int r, int c, int M, int N,
                                          int ldc, const float* bias, float* C,
                                          f16* Ch, f16* Cl) {
    if (r >= M || c >= N) return;
    if (EPI == 1 || EPI == 3 || EPI == 4 || EPI == 6 || EPI == 7) v += bias[c];
    if (EPI == 7) {
        int b = r >> 9, l = r & (L_ - 1), h = c >> 7, d = c & 127;
        long orow = ((long)b * (H_ * L_) + h * L_ + l) * (2 * DS);
        split2(v * v,   Ch + orow + d,      Cl + orow + d);
        split2(-2.f * v, Ch + orow + DS + d, Cl + orow + DS + d);
        return;
    }
    long off = (long)r * ldc + c;
    if (EPI == 0 || EPI == 1) C[off] = v;
    else if (EPI == 3) {
        v = 0.5f * v * (1.0f + erff(v * 0.7071067811865476f));
        split2(v, Ch + off, Cl + off);
    } else if (EPI == 4) {
        float nv = C[off] + v;
        C[off] = nv;
        split2(nv, Ch + off, Cl + off);
    } else if (EPI == 5) {
        split2(v, Ch + off, Cl + off);
    } else if (EPI == 6) {
        C[off] = v;
        split2(v, Ch + off, Cl + off);
    }
}

#define KT         64
#define SMEM_STAGE 65536
#define SMEM_TOT   (3 * SMEM_STAGE)

// flags: bit0 = causal N-tile skip (period 512); bit1 = causal K clamp;
//        bit2 = split-K chunk clamp (K = min(K, ldab - z2*K)).
// NTERMS: 2 = Ah*Bh + Al*Bh (B single-rounded fp16); 1 = Ah*Bh only.
template<int EPI, int NTERMS>
__global__ void __launch_bounds__(256) mma_gemm_k(
    const f16* __restrict__ Ah, const f16* __restrict__ Al,
    const f16* __restrict__ Bh,
    const float* __restrict__ bias, float* __restrict__ C,
    f16* __restrict__ Ch, f16* __restrict__ Cl,
    int M, int N, int K, int ldab, int ldc,
    long sA1, long sA2, long sB1, long sB2, long sC1, long sC2, int n2,
    int flags)
{
    extern __shared__ __align__(16) unsigned char smem_raw[];
    const uint32_t sbase = (uint32_t)__cvta_generic_to_shared(smem_raw);

    const int bm = blockIdx.x * 128;   // M fast -> better L2 reuse of B stripes
    const int bn = blockIdx.y * 128;

    if ((flags & 1) && bn >= (bm & 511) + 128) return;   // causal skip
    if (flags & 2) { int ke = (bm & 511) + 128; if (ke < K) K = ke; }

    int z  = blockIdx.z;
    int z1 = z / n2, z2 = z - z1 * n2;
    if (flags & 4) { int rem = ldab - z2 * K; if (rem < K) K = rem; }
    Ah += (long)z1 * sA1 + (long)z2 * sA2;
    if (NTERMS >= 2) Al += (long)z1 * sA1 + (long)z2 * sA2;
    Bh += (long)z1 * sB1 + (long)z2 * sB2;
    long coff = (long)z1 * sC1 + (long)z2 * sC2;
    if (C)  C  += coff;
    if (Ch) { Ch += coff; Cl += coff; }

    const int tid  = threadIdx.x;
    const int lane = tid & 31;
    const int warp = tid >> 5;
    const int wm = warp >> 2;      // 0..1
    const int wn = warp & 3;       // 0..3
    const int kso = wm << 1;       // ks phase skew: SMSP pairs {w, w+4} anti-phase

    float acc[4][4][4];
    #pragma unroll
    for (int i = 0; i < 4; i++)
        #pragma unroll
        for (int j = 0; j < 4; j++)
            #pragma unroll
            for (int e = 0; e < 4; e++) acc[i][j][e] = 0.f;

    const int T = (K + KT - 1) / KT;

    auto load_stage = [&](int st, int kt) {
        const uint32_t sb = sbase + st * SMEM_STAGE;
        const int k0 = kt * KT;
        #pragma unroll
        for (int it = 0; it < 4; it++) {
            int cch = tid + it * 256;            // 0..1023
            int row = cch >> 3, u = cch & 7;
            int gk = k0 + u * 8;
            bool kok = gk < K;
            int gkc = kok ? gk : 0;
            uint32_t sw = row * 128 + ((u ^ (row & 7)) << 4);
            {   // A
                int gm = bm + row;
                bool p = kok && (gm < M);
                long off = (long)(p ? gm : 0) * ldab + gkc;
                cpa16(sb + sw, Ah + off, p);
                if (NTERMS >= 2) cpa16(sb + 16384 + sw, Al + off, p);
            }
            {   // B
                int gn = bn + row;
                bool p = kok && (gn < N);
                long off = (long)(p ? gn : 0) * ldab + gkc;
                cpa16(sb + 32768 + sw, Bh + off, p);
            }
        }
    };

    // prologue: stages 0 and 1
    load_stage(0, 0);
    cpa_commit();
    if (1 < T) load_stage(1, 1);
    cpa_commit();

    for (int t = 0; t < T; t++) {
        cpa_wait<1>();
        __syncthreads();

        if (t + 2 < T) load_stage((t + 2) % 3, t + 2);
        cpa_commit();                         // unconditional: keeps group math exact

        const uint32_t sb  = sbase + (t % 3) * SMEM_STAGE;
        const uint32_t sAh = sb, sAl = sb + 16384, sBh = sb + 32768;

        auto loadB = [&](int ks, uint32_t* bf) {
            const int kb = ks * 16;
            #pragma unroll
            for (int p2 = 0; p2 < 2; p2++) {
                int n_ = wn * 32 + p2 * 16 + (lane & 7) + ((lane >> 4) << 3);
                int kc = kb + (((lane >> 3) & 1) << 3);
                uint32_t off = n_ * 128 + ((((kc >> 3) ^ (n_ & 7))) << 4);
                ldsm4(bf[p2*4+0], bf[p2*4+1], bf[p2*4+2], bf[p2*4+3], sBh + off);
            }
        };
        auto loadA = [&](int ks, int i, uint32_t* fh, uint32_t* fl) {
            const int kb = ks * 16;
            int r_ = wm * 64 + i * 16 + (lane & 7) + (((lane >> 3) & 1) << 3);
            int kc = kb + ((lane >> 4) << 3);
            uint32_t off = r_ * 128 + ((((kc >> 3) ^ (r_ & 7))) << 4);
            ldsm4(fh[0], fh[1], fh[2], fh[3], sAh + off);
            if (NTERMS >= 2) ldsm4(fl[0], fl[1], fl[2], fl[3], sAl + off);
        };

        // register-level software pipeline: A double-buffered at i-granularity,
        // B double-buffered at ks-granularity -> every ldsm is >=16 mma ahead
        // of its first consumer. mma order per accumulator unchanged.
        uint32_t bf[2][8], afh[2][4], afl[2][4];
        loadB(kso & 3, bf[0]);
        loadA(kso & 3, 0, afh[0], afl[0]);
        #pragma unroll
        for (int ksi = 0; ksi < 4; ksi++) {
            const int ks = (ksi + kso) & 3;     // phase skew across SMSP pairs
            const int cb = ksi & 1;
            if (ksi < 3) loadB((ksi + 1 + kso) & 3, bf[cb ^ 1]);
            #pragma unroll
            for (int i = 0; i < 4; i++) {
                const int ca = (ksi * 4 + i) & 1;
                if (i < 3)
                    loadA(ks, i + 1, afh[ca ^ 1], afl[ca ^ 1]);
                else if (ksi < 3)
                    loadA((ksi + 1 + kso) & 3, 0, afh[ca ^ 1], afl[ca ^ 1]);
                #pragma unroll
                for (int j = 0; j < 4; j++) {
                    int bi = (j >> 1) * 4 + (j & 1) * 2;
                    mma_f16(acc[i][j], afh[ca], bf[cb][bi], bf[cb][bi+1]);
                    if (NTERMS >= 2)
                        mma_f16(acc[i][j], afl[ca], bf[cb][bi], bf[cb][bi+1]);
                }
            }
        }
        __syncthreads();
    }

    // ---- epilogue ----
    #pragma unroll
    for (int i = 0; i < 4; i++) {
        int r0 = bm + wm * 64 + i * 16 + (lane >> 2);
        #pragma unroll
        for (int j = 0; j < 4; j++) {
            int c0 = bn + wn * 32 + j * 8 + ((lane & 3) << 1);
            epi_store<EPI>(acc[i][j][0], r0,     c0,     M, N, ldc, bias, C, Ch, Cl);
            epi_store<EPI>(acc[i][j][1], r0,     c0 + 1, M, N, ldc, bias, C, Ch, Cl);
            epi_store<EPI>(acc[i][j][2], r0 + 8, c0,     M, N, ldc, bias, C, Ch, Cl);
            epi_store<EPI>(acc[i][j][3], r0 + 8, c0 + 1, M, N, ldc, bias, C, Ch, Cl);
        }
    }
}

// ---------------- split / round / transpose kernels ------------------------
__global__ void split_k(const float4* __restrict__ x, uint4* __restrict__ h,
                        uint4* __restrict__ l, long n8)
{
    long i = (long)blockIdx.x * 256 + threadIdx.x;
    if (i >= n8) return;
    float4 a = x[2 * i], b = x[2 * i + 1];
    float vs[8] = {a.x, a.y, a.z, a.w, b.x, b.y, b.z, b.w};
    f16 hv[8], lv[8];
    #pragma unroll
    for (int j = 0; j < 8; j++) split2(vs[j], &hv[j], &lv[j]);
    h[i] = *(uint4*)hv;
    l[i] = *(uint4*)lv;
}

__global__ void round_k(const float4* __restrict__ x, uint4* __restrict__ h,
                        long n8)
{
    long i = (long)blockIdx.x * 256 + threadIdx.x;
    if (i >= n8) return;
    float4 a = x[2 * i], b = x[2 * i + 1];
    float vs[8] = {a.x, a.y, a.z, a.w, b.x, b.y, b.z, b.w};
    f16 hv[8];
    #pragma unroll
    for (int j = 0; j < 8; j++) hv[j] = __float2half_rn(vs[j]);
    h[i] = *(uint4*)hv;
}

// feats [b, l, :DF] (ld 2DF) -> out [b, f, l] hi only
__global__ void splitT_k(const float* __restrict__ x, f16* __restrict__ oh)
{
    __shared__ float t[32][33];
    int b  = blockIdx.z;
    int j0 = blockIdx.y * 32;
    int f0 = blockIdx.x * 32;
    const float* xb = x + (long)b * L_ * 2 * DF;
    int tx = threadIdx.x, ty = threadIdx.y;
    #pragma unroll
    for (int s = 0; s < 32; s += 8) {
        int j = j0 + ty + s, f = f0 + tx;
        t[ty + s][tx] = (f < DF) ? xb[(long)j * 2 * DF + f] : 0.f;
    }
    __syncthreads();
    #pragma unroll
    for (int s = 0; s < 32; s += 8) {
        int f = f0 + ty + s, j = j0 + tx;
        if (f < DF) {
            long o = ((long)b * DF + f) * L_ + j;
            oh[o] = __float2half_rn(t[tx][ty + s]);
        }
    }
}

// ---------------- model-specific small kernels -----------------------------
__global__ void gather_k(const int* __restrict__ tokens,
                         const float* __restrict__ tok_mu,
                         const float* __restrict__ tok_lv,
                         const float* __restrict__ tok_ra,
                         const float* __restrict__ tok_ft,
                         const float* __restrict__ pos_mu,
                         float* __restrict__ mu, float* __restrict__ iv,
                         float* __restrict__ alpha, float* __restrict__ xbuf,
                         f16* __restrict__ xh, f16* __restrict__ xl)
{
    int row = blockIdx.x;
    int l   = row & (L_ - 1);
    int tok = tokens[row];
    for (int d = threadIdx.x; d < DS; d += blockDim.x) {
        mu[row * DS + d] = tok_mu[(long)tok * DS + d] + pos_mu[l * DS + d];
        iv[row * DS + d] = expf(-tok_lv[(long)tok * DS + d]);
    }
    if (threadIdx.x == 0)
        alpha[row] = 1.f / (1.f + expf(-tok_ra[tok]));
    for (int f = threadIdx.x; f < DF; f += blockDim.x) {
        float v = tok_ft[(long)tok * DF + f];
        long o = (long)row * 2 * DF + f;
        xbuf[o] = v;
        split2(v, xh + o, xl + o);
    }
}

__global__ void prep_k(const float* __restrict__ mu, const float* __restrict__ iv,
                       float* __restrict__ mu2,
                       f16* muh, f16* mul_, f16* ivh, f16* ivl)
{
    int row = blockIdx.x;
    int d   = threadIdx.x;            // 128
    float m  = mu[row * DS + d];
    float v  = iv[row * DS + d];
    float miv = m * v;
    split2(m,   muh + row * DS + d,       mul_ + row * DS + d);
    split2(v,   ivh + row * 2 * DS + d,       ivl + row * 2 * DS + d);
    split2(miv, ivh + row * 2 * DS + DS + d,  ivl + row * 2 * DS + DS + d);
    float s = warpSum(m * miv);
    __shared__ float sm[4];
    if ((d & 31) == 0) sm[d >> 5] = s;
    __syncthreads();
    if (d == 0) mu2[row] = sm[0] + sm[1] + sm[2] + sm[3];
}

// mu += tanh(sum of 4 split-K partials + bias)
__global__ void mu_red_k(const float* __restrict__ part,
                         const float* __restrict__ bmu, float* __restrict__ mu)
{
    int i = blockIdx.x * 256 + threadIdx.x;        // BL*DS total
    float s = part[i] + part[i + BL * DS] + part[i + 2 * BL * DS]
            + part[i + 3 * BL * DS] + bmu[i & (DS - 1)];
    mu[i] += tanhf(s);
}

__global__ void __launch_bounds__(512) scan_k(const float* __restrict__ mahal,
                                              const float* __restrict__ alpha,
                                              const float* __restrict__ mu2,
                                              const float* __restrict__ log_tau,
                                              f16* __restrict__ wh,
                                              f16* __restrict__ wl)
{
    int row = blockIdx.x;
    int b = row >> 11;
    int l = row & (L_ - 1);
    int j = threadIdx.x;
    float tau = expf(log_tau[0]);
    long off = (long)row * L_ + j;
    float eff = 0.f;
    if (j <= l) {
        float m  = mahal[off] + mu2[b * L_ + j];
        float Kv = expf(-0.5f * m / tau);
        eff = fminf(alpha[b * L_ + j] * Kv, 1.f - 1e-6f);
    }
    float gv = log1pf(-eff);

    int lane = j & 31, warp = j >> 5;
    float incl = gv;
    #pragma unroll
    for (int o = 1; o < 32; o <<= 1) {
        float t = __shfl_up_sync(0xffffffffu, incl, o);
        if (lane >= o) incl += t;
    }
    __shared__ float ws[16];
    if (lane == 31) ws[warp] = incl;
    __syncthreads();
    if (warp == 0) {
        float t = (lane < 16) ? ws[lane] : 0.f;
        #pragma unroll
        for (int o = 1; o < 16; o <<= 1) {
            float u = __shfl_up_sync(0xffffffffu, t, o);
            if (lane >= o) t += u;
        }
        if (lane < 16) ws[lane] = t;
    }
    __syncthreads();
    float prefix = warp ? ws[warp - 1] : 0.f;
    incl += prefix;
    float w = eff * expf(incl - gv);
    split2(w, wh + off, wl + off);
}

__global__ void ln_k(const float* __restrict__ x, f16* __restrict__ yh,
                     f16* __restrict__ yl,
                     const float* __restrict__ g, const float* __restrict__ b,
                     int n, int ldx, int ldy)
{
    __shared__ float red[32];
    int row = blockIdx.x;
    const float* xr = x + (long)row * ldx;
    float s = 0.f;
    for (int i = threadIdx.x; i < n; i += blockDim.x) s += xr[i];
    s = blockSum(s, red);
    float mean = s / n;
    float v = 0.f;
    for (int i = threadIdx.x; i < n; i += blockDim.x) {
        float d = xr[i] - mean;
        v += d * d;
    }
    v = blockSum(v, red);
    float rstd = rsqrtf(v / n + 1e-5f);
    for (int i = threadIdx.x; i < n; i += blockDim.x) {
        float val = (xr[i] - mean) * rstd * g[i] + b[i];
        long o = (long)row * ldy + i;
        split2(val, yh + o, yl + o);
    }
}

__global__ void alpha_gate_k(const float* __restrict__ x, const float* __restrict__ Wg,
                             const float* __restrict__ bg, float* __restrict__ alpha)
{
    __shared__ float red[32];
    int row = blockIdx.x;
    const float* xr = x + (long)row * 2 * DF;
    float s = 0.f;
    for (int i = threadIdx.x; i < 2 * DF; i += blockDim.x) s += xr[i] * Wg[i];
    s = blockSum(s, red) + bg[0];
    if (threadIdx.x == 0) alpha[row] *= 1.f / (1.f + expf(-s));
}

// ---------------- host side -------------------------------------------------
static void launch_mma(int epi, int terms,
                       const f16* Ah, const f16* Al, const f16* Bh,
                       const float* bias, float* C, f16* Ch, f16* Cl,
                       int M, int N, int K, int ldab, int ldc,
                       long sA1, long sA2, long sB1, long sB2, long sC1, long sC2,
                       int n1, int n2, int flags)
{
    dim3 grid((M + 127) / 128, (N + 127) / 128, n1 * n2);
    #define MARGS Ah, Al, Bh, bias, C, Ch, Cl, M, N, K, ldab, ldc, sA1, sA2, sB1, sB2, sC1, sC2, n2, flags
    switch (epi * 10 + terms) {
        case  1: mma_gemm_k<0, 1><<<grid, 256, SMEM_TOT>>>(MARGS); break;
        case  2: mma_gemm_k<0, 2><<<grid, 256, SMEM_TOT>>>(MARGS); break;
        case 12: mma_gemm_k<1, 2><<<grid, 256, SMEM_TOT>>>(MARGS); break;
        case 32: mma_gemm_k<3, 2><<<grid, 256, SMEM_TOT>>>(MARGS); break;
        case 42: mma_gemm_k<4, 2><<<grid, 256, SMEM_TOT>>>(MARGS); break;
        case 52: mma_gemm_k<5, 2><<<grid, 256, SMEM_TOT>>>(MARGS); break;
        case 62: mma_gemm_k<6, 2><<<grid, 256, SMEM_TOT>>>(MARGS); break;
        case 72: mma_gemm_k<7, 2><<<grid, 256, SMEM_TOT>>>(MARGS); break;
    }
    #undef MARGS
}

static void run_round(const float* x, f16* h, long n) {
    long n8 = n / 8;
    round_k<<<(unsigned)((n8 + 255) / 256), 256>>>((const float4*)x, (uint4*)h, n8);
}

extern "C" void kernel_launch(void* const* d_in, const int* in_sizes, int n_in,
                              void* d_out, int out_size)
{
    const int*   tokens  = (const int*)  d_in[0];
    const float* tok_mu  = (const float*)d_in[1];
    const float* tok_lv  = (const float*)d_in[2];
    const float* tok_ra  = (const float*)d_in[3];
    const float* tok_ft  = (const float*)d_in[4];
    const float* pos_mu  = (const float*)d_in[5];
    const float* log_tau = (const float*)d_in[6];
    const float* Wq      = (const float*)d_in[7];
    const float* bq      = (const float*)d_in[8];
    const float* Whead   = (const float*)d_in[9];
    const float* bhead   = (const float*)d_in[10];
    const float* Wmu     = (const float*)d_in[11];
    const float* bmu     = (const float*)d_in[12];
    const float* Wg      = (const float*)d_in[13];
    const float* bg      = (const float*)d_in[14];
    const float* ln_g    = (const float*)d_in[15];
    const float* ln_b    = (const float*)d_in[16];
    const float* W1      = (const float*)d_in[17];
    const float* b1      = (const float*)d_in[18];
    const float* W2      = (const float*)d_in[19];
    const float* b2      = (const float*)d_in[20];
    const float* lnf_g   = (const float*)d_in[21];
    const float* lnf_b   = (const float*)d_in[22];
    const float* Wlm     = (const float*)d_in[23];
    float* out = (float*)d_out;

    cudaFuncSetAttribute(mma_gemm_k<0,1>, cudaFuncAttributeMaxDynamicSharedMemorySize, SMEM_TOT);
    cudaFuncSetAttribute(mma_gemm_k<0,2>, cudaFuncAttributeMaxDynamicSharedMemorySize, SMEM_TOT);
    cudaFuncSetAttribute(mma_gemm_k<1,2>, cudaFuncAttributeMaxDynamicSharedMemorySize, SMEM_TOT);
    cudaFuncSetAttribute(mma_gemm_k<3,2>, cudaFuncAttributeMaxDynamicSharedMemorySize, SMEM_TOT);
    cudaFuncSetAttribute(mma_gemm_k<4,2>, cudaFuncAttributeMaxDynamicSharedMemorySize, SMEM_TOT);
    cudaFuncSetAttribute(mma_gemm_k<5,2>, cudaFuncAttributeMaxDynamicSharedMemorySize, SMEM_TOT);
    cudaFuncSetAttribute(mma_gemm_k<6,2>, cudaFuncAttributeMaxDynamicSharedMemorySize, SMEM_TOT);
    cudaFuncSetAttribute(mma_gemm_k<7,2>, cudaFuncAttributeMaxDynamicSharedMemorySize, SMEM_TOT);

    float *mu, *iv, *mu2, *alpha, *mahal, *xbuf, *part;
    cudaGetSymbolAddress((void**)&mu,    g_mu);
    cudaGetSymbolAddress((void**)&iv,    g_iv);
    cudaGetSymbolAddress((void**)&mu2,   g_mu2);
    cudaGetSymbolAddress((void**)&alpha, g_alpha);
    cudaGetSymbolAddress((void**)&mahal, g_mahal);
    cudaGetSymbolAddress((void**)&xbuf,  g_xbuf);
    cudaGetSymbolAddress((void**)&part,  g_part);

    f16 *muh, *mul_, *ivh, *ivl, *qeh, *qel, *wh, *wl, *fth,
        *mhh, *mhl, *xh, *xl, *hh, *hl, *h1h, *h1l;
    f16 *wqh, *whdh, *wmuh, *w1h, *w2h, *wlmh;
    cudaGetSymbolAddress((void**)&muh,  g_muh);  cudaGetSymbolAddress((void**)&mul_, g_mul);
    cudaGetSymbolAddress((void**)&ivh,  g_ivh);  cudaGetSymbolAddress((void**)&ivl,  g_ivl);
    cudaGetSymbolAddress((void**)&qeh,  g_qeh);  cudaGetSymbolAddress((void**)&qel,  g_qel);
    cudaGetSymbolAddress((void**)&wh,   g_wh);   cudaGetSymbolAddress((void**)&wl,   g_wl);
    cudaGetSymbolAddress((void**)&fth,  g_fth);
    cudaGetSymbolAddress((void**)&mhh,  g_mhh);  cudaGetSymbolAddress((void**)&mhl,  g_mhl);
    cudaGetSymbolAddress((void**)&xh,   g_xh);   cudaGetSymbolAddress((void**)&xl,   g_xl);
    cudaGetSymbolAddress((void**)&hh,   g_hh);   cudaGetSymbolAddress((void**)&hl,   g_hl);
    cudaGetSymbolAddress((void**)&h1h,  g_h1h);  cudaGetSymbolAddress((void**)&h1l,  g_h1l);
    cudaGetSymbolAddress((void**)&wqh,  g_wqh);
    cudaGetSymbolAddress((void**)&whdh, g_whdh);
    cudaGetSymbolAddress((void**)&wmuh, g_wmuh);
    cudaGetSymbolAddress((void**)&w1h,  g_w1h);
    cudaGetSymbolAddress((void**)&w2h,  g_w2h);
    cudaGetSymbolAddress((void**)&wlmh, g_wlmh);

    // weight conversions (every call; deterministic) — all single-rounded
    run_round(Wq,    wqh,  (long)512 * DS);
    run_round(Whead, whdh, (long)DF * H_ * DF);
    run_round(Wmu,   wmuh, (long)2 * DS * 2 * DF);
    run_round(W1,    w1h,  (long)2 * 4 * DF * 2 * DF);
    run_round(W2,    w2h,  (long)2 * DF * 4 * DF);
    run_round(Wlm,   wlmh, (long)V_ * DF);

    gather_k<<<BL, 256>>>(tokens, tok_mu, tok_lv, tok_ra, tok_ft, pos_mu,
                          mu, iv, alpha, xbuf, xh, xl);

    for (int p = 0; p < 3; p++) {
        prep_k<<<BL, 128>>>(mu, iv, mu2, muh, mul_, ivh, ivl);

        // q = mu @ Wq^T + bq, packed directly into qe (EPI 7)
        launch_mma(7, 2, muh, mul_, wqh, bq, nullptr, qeh, qel,
                   BL, H_ * DS, DS, DS, 0, 0, 0, 0, 0, 0, 0, 1, 1, 0);

        // mahal (without +mu2): single f16 term (tau-damped), causal-N skip
        launch_mma(0, 1, qeh, qel, ivh, nullptr, mahal, nullptr, nullptr,
                   H_ * L_, L_, 2 * DS, 2 * DS, L_,
                   (long)(H_ * L_) * 2 * DS, 0,
                   (long)L_ * 2 * DS, 0,
                   (long)(H_ * L_) * L_, 0, B_, 1, 1);

        scan_k<<<BHL, 512>>>(mahal, alpha, mu2, log_tau, wh, wl);

        // feats^T hi only (2-term B)
        splitT_k<<<dim3(32, 16, B_), dim3(32, 8)>>>(xbuf, fth);

        // mh = w @ feats^T (causal-K clamp), 2-term, split-out
        launch_mma(5, 2, wh, wl, fth, nullptr, nullptr, mhh, mhl,
                   L_, DF, L_, L_, H_ * DF,
                   (long)(H_ * L_) * L_, (long)L_ * L_,
                   (long)DF * L_, 0,
                   (long)L_ * H_ * DF, DF, B_, H_, 2);

        if (p < 2) {
            // meaning = mh @ Whead^T + bhead (2-term) -> xbuf fp32 AND xh/xl (+DF)
            launch_mma(6, 2, mhh, mhl, whdh, bhead, xbuf + DF, xh + DF, xl + DF,
                       BL, DF, H_ * DF, H_ * DF, 2 * DF,
                       0, 0, 0, 0, 0, 0, 1, 1, 0);

            alpha_gate_k<<<BL, 256>>>(xbuf, Wg + p * 2 * DF, bg + p, alpha);

            // mu-update split-K: partials = x @ Wmu[p]^T (4 K-chunks of 512)
            launch_mma(0, 2, xh, xl, wmuh + (long)p * DS * 2 * DF,
                       nullptr, part, nullptr, nullptr,
                       BL, DS, 512, 2 * DF, DS,
                       0, 512, 0, 512, 0, (long)BL * DS, 1, 4, 4);
            mu_red_k<<<BL * DS / 256, 256>>>(part, bmu + p * DS, mu);

            // h = LN(x) (hi/lo)
            ln_k<<<BL, 256>>>(xbuf, hh, hl, ln_g + p * 2 * DF, ln_b + p * 2 * DF,
                              2 * DF, 2 * DF, 2 * DF);

            // h1 = gelu(h @ W1[p]^T + b1[p]) split-out (2-term)
            launch_mma(3, 2, hh, hl, w1h + (long)p * 4 * DF * 2 * DF,
                       b1 + p * 4 * DF, nullptr, h1h, h1l,
                       BL, 4 * DF, 2 * DF, 2 * DF, 4 * DF,
                       0, 0, 0, 0, 0, 0, 1, 1, 0);

            // feats += h1 @ W2[p]^T + b2[p] : fp32 AND split (2-term)
            launch_mma(4, 2, h1h, h1l, w2h + (long)p * DF * 4 * DF,
                       b2 + p * DF, xbuf, xh, xl,
                       BL, DF, 4 * DF, 4 * DF, 2 * DF,
                       0, 0, 0, 0, 0, 0, 1, 1, 0);
        } else {
            // final-pass meaning: feeds only LN+LM head -> 2-term, fp32 only
            launch_mma(1, 2, mhh, mhl, whdh, bhead, xbuf + DF,
                       nullptr, nullptr,
                       BL, DF, H_ * DF, H_ * DF, 2 * DF,
                       0, 0, 0, 0, 0, 0, 1, 1, 0);
        }
    }

    // y = LN(meaning); logits = y @ Wlm^T  (1-term: A hi, B hi)
    ln_k<<<BL, 256>>>(xbuf + DF, hh, hl, lnf_g, lnf_b, DF, 2 * DF, DF);
    launch_mma(0, 1, hh, nullptr, wlmh, nullptr, out, nullptr, nullptr,
               BL, V_, DF, DF, V_, 0, 0, 0, 0, 0, 0, 1, 1, 0);
}

// round 14
// speedup vs baseline: 1.1271x; 1.1271x over previous
#include <cuda_runtime.h>
#include <cuda_fp16.h>
#include <math.h>
#include <stdint.h>

#define B_  4
#define L_  512
#define DS  128
#define DF  1000
#define H_  4
#define V_  32000
#define BL  2048    /* B*L   */
#define BHL 8192    /* B*H*L */

typedef __half f16;

// ---------------- fp32 scratch -------------------------------------------
__device__ float g_mu   [BL * DS];
__device__ float g_iv   [BL * DS];
__device__ float g_mu2  [BL];
__device__ float g_alpha[BL];
__device__ float g_mahal[(size_t)BHL * L_];
__device__ float g_xbuf [(size_t)BL * 2 * DF];
__device__ float g_part [4 * BL * DS];          // split-K partials for mu GEMM

// ---------------- fp16 scratch ---------------------------------------------
__device__ f16 g_muh[BL * DS],        g_mul[BL * DS];
__device__ f16 g_ivh[BL * 2 * DS],    g_ivl[BL * 2 * DS];
__device__ f16 g_qeh[BHL * 2 * DS],   g_qel[BHL * 2 * DS];
__device__ f16 g_wh [(size_t)BHL * L_];                   // 1-term w
__device__ f16 g_fth[(size_t)B_ * DF * L_];               // hi only
__device__ f16 g_mhh[(size_t)BL * H_ * DF];               // 1-term mh
__device__ f16 g_xh [(size_t)BL * 2 * DF],   g_xl [(size_t)BL * 2 * DF];
__device__ f16 g_hh [(size_t)BL * 2 * DF],   g_hl [(size_t)BL * 2 * DF];
__device__ f16 g_h1h[(size_t)BL * 4 * DF],   g_h1l[(size_t)BL * 4 * DF];
// weights (all single-rounded fp16)
__device__ f16 g_wqh[512 * DS];
__device__ f16 g_whdh[(size_t)DF * H_ * DF];
__device__ f16 g_wmuh[(size_t)2 * DS * 2 * DF];
__device__ f16 g_w1h[(size_t)2 * 4 * DF * 2 * DF];
__device__ f16 g_w2h[(size_t)2 * DF * 4 * DF];
__device__ f16 g_wlmh[(size_t)V_ * DF];

// ---------------- helpers --------------------------------------------------
__device__ __forceinline__ float warpSum(float v) {
    #pragma unroll
    for (int o = 16; o > 0; o >>= 1) v += __shfl_down_sync(0xffffffffu, v, o);
    return v;
}
__device__ float blockSum(float v, float* red) {
    int lane = threadIdx.x & 31, w = threadIdx.x >> 5;
    v = warpSum(v);
    __syncthreads();
    if (lane == 0) red[w] = v;
    __syncthreads();
    if (w == 0) {
        int nw = (blockDim.x + 31) >> 5;
        float t = (lane < nw) ? red[lane] : 0.f;
        t = warpSum(t);
        if (lane == 0) red[0] = t;
    }
    __syncthreads();
    return red[0];
}
__device__ __forceinline__ void split2(float v, f16* ph, f16* pl) {
    f16 h = __float2half_rn(v);
    *ph = h;
    *pl = __float2half_rn(v - __half2float(h));
}

// ---------------- mma.sync GEMM engine -------------------------------------
__device__ __forceinline__ void ldsm4(uint32_t& r0, uint32_t& r1, uint32_t& r2,
                                      uint32_t& r3, uint32_t a) {
    asm volatile("ldmatrix.sync.aligned.m8n8.x4.shared.b16 {%0,%1,%2,%3}, [%4];"
                 : "=r"(r0), "=r"(r1), "=r"(r2), "=r"(r3) : "r"(a));
}
__device__ __forceinline__ void mma_f16(float* c, const uint32_t* a,
                                        uint32_t b0, uint32_t b1) {
    asm volatile(
        "mma.sync.aligned.m16n8k16.row.col.f32.f16.f16.f32 "
        "{%0,%1,%2,%3}, {%4,%5,%6,%7}, {%8,%9}, {%0,%1,%2,%3};"
        : "+f"(c[0]), "+f"(c[1]), "+f"(c[2]), "+f"(c[3])
        : "r"(a[0]), "r"(a[1]), "r"(a[2]), "r"(a[3]), "r"(b0), "r"(b1));
}
__device__ __forceinline__ void cpa16(uint32_t dst, const void* src, bool p) {
    asm volatile("cp.async.cg.shared.global [%0], [%1], 16, %2;"
                 :: "r"(dst), "l"(src), "r"(p ? 16 : 0));
}
__device__ __forceinline__ void cpa_commit() {
    asm volatile("cp.async.commit_group;");
}
template<int NN>
__device__ __forceinline__ void cpa_wait() {
    asm volatile("cp.async.wait_group %0;" :: "n"(NN));
}

// EPI: 0 C=v; 1 C=v+bias; 3 split-out gelu(v+bias);
//      4 Cf=C+v+bias, also split Cf -> Ch/Cl;
//      6 C=v+bias, also split -> Ch/Cl;
//      7 qe-pack; 8 Ch=round(v)
template<int EPI>
__device__ __forceinline__ void epi_store(float v, int r, int c, int M, int N,
                                          int ldc, const float* bias, float* C,
                                          f16* Ch, f16* Cl) {
    if (r >= M || c >= N) return;
    if (EPI == 1 || EPI == 3 || EPI == 4 || EPI == 6 || EPI == 7) v += bias[c];
    if (EPI == 7) {
        int b = r >> 9, l = r & (L_ - 1), h = c >> 7, d = c & 127;
        long orow = ((long)b * (H_ * L_) + h * L_ + l) * (2 * DS);
        split2(v * v,   Ch + orow + d,      Cl + orow + d);
        split2(-2.f * v, Ch + orow + DS + d, Cl + orow + DS + d);
        return;
    }
    long off = (long)r * ldc + c;
    if (EPI == 0 || EPI == 1) C[off] = v;
    else if (EPI == 3) {
        v = 0.5f * v * (1.0f + erff(v * 0.7071067811865476f));
        split2(v, Ch + off, Cl + off);
    } else if (EPI == 4) {
        float nv = C[off] + v;
        C[off] = nv;
        split2(nv, Ch + off, Cl + off);
    } else if (EPI == 6) {
        C[off] = v;
        split2(v, Ch + off, Cl + off);
    } else if (EPI == 8) {
        Ch[off] = __float2half_rn(v);
    }
}

#define KT         64
#define SMEM_STAGE 65536
#define SMEM_TOT   (3 * SMEM_STAGE)

// flags: bit0 = causal N-tile skip (period 512); bit1 = causal K clamp;
//        bit2 = split-K chunk clamp.
// NTERMS: 2 = Ah*Bh + Al*Bh; 1 = Ah*Bh only.
template<int EPI, int NTERMS>
__global__ void __launch_bounds__(256) mma_gemm_k(
    const f16* __restrict__ Ah, const f16* __restrict__ Al,
    const f16* __restrict__ Bh,
    const float* __restrict__ bias, float* __restrict__ C,
    f16* __restrict__ Ch, f16* __restrict__ Cl,
    int M, int N, int K, int ldab, int ldc,
    long sA1, long sA2, long sB1, long sB2, long sC1, long sC2, int n2,
    int flags)
{
    extern __shared__ __align__(16) unsigned char smem_raw[];
    const uint32_t sbase = (uint32_t)__cvta_generic_to_shared(smem_raw);

    const int bm = blockIdx.x * 128;   // M fast -> better L2 reuse of B stripes
    const int bn = blockIdx.y * 128;

    if ((flags & 1) && bn >= (bm & 511) + 128) return;   // causal skip
    if (flags & 2) { int ke = (bm & 511) + 128; if (ke < K) K = ke; }

    int z  = blockIdx.z;
    int z1 = z / n2, z2 = z - z1 * n2;
    if (flags & 4) { int rem = ldab - z2 * K; if (rem < K) K = rem; }
    Ah += (long)z1 * sA1 + (long)z2 * sA2;
    if (NTERMS >= 2) Al += (long)z1 * sA1 + (long)z2 * sA2;
    Bh += (long)z1 * sB1 + (long)z2 * sB2;
    long coff = (long)z1 * sC1 + (long)z2 * sC2;
    if (C)  C  += coff;
    if (Ch) { Ch += coff; if (Cl) Cl += coff; }

    const int tid  = threadIdx.x;
    const int lane = tid & 31;
    const int warp = tid >> 5;
    const int wm = warp >> 2;      // 0..1
    const int wn = warp & 3;       // 0..3
    const int kso = wm << 1;       // ks phase skew: SMSP pairs {w, w+4} anti-phase

    float acc[4][4][4];
    #pragma unroll
    for (int i = 0; i < 4; i++)
        #pragma unroll
        for (int j = 0; j < 4; j++)
            #pragma unroll
            for (int e = 0; e < 4; e++) acc[i][j][e] = 0.f;

    const int T = (K + KT - 1) / KT;

    auto load_stage = [&](int st, int kt) {
        const uint32_t sb = sbase + st * SMEM_STAGE;
        const int k0 = kt * KT;
        #pragma unroll
        for (int it = 0; it < 4; it++) {
            int cch = tid + it * 256;            // 0..1023
            int row = cch >> 3, u = cch & 7;
            int gk = k0 + u * 8;
            bool kok = gk < K;
            int gkc = kok ? gk : 0;
            uint32_t sw = row * 128 + ((u ^ (row & 7)) << 4);
            {   // A
                int gm = bm + row;
                bool p = kok && (gm < M);
                long off = (long)(p ? gm : 0) * ldab + gkc;
                cpa16(sb + sw, Ah + off, p);
                if (NTERMS >= 2) cpa16(sb + 16384 + sw, Al + off, p);
            }
            {   // B
                int gn = bn + row;
                bool p = kok && (gn < N);
                long off = (long)(p ? gn : 0) * ldab + gkc;
                cpa16(sb + 32768 + sw, Bh + off, p);
            }
        }
    };

    // prologue: stages 0 and 1
    load_stage(0, 0);
    cpa_commit();
    if (1 < T) load_stage(1, 1);
    cpa_commit();

    for (int t = 0; t < T; t++) {
        cpa_wait<1>();
        __syncthreads();

        if (t + 2 < T) load_stage((t + 2) % 3, t + 2);
        cpa_commit();                         // unconditional: keeps group math exact

        const uint32_t sb  = sbase + (t % 3) * SMEM_STAGE;
        const uint32_t sAh = sb, sAl = sb + 16384, sBh = sb + 32768;

        #pragma unroll
        for (int ksi = 0; ksi < 4; ksi++) {
            const int ks = (ksi + kso) & 3;     // phase skew across SMSP pairs
            const int kb = ks * 16;
            uint32_t bhf[8];
            #pragma unroll
            for (int p2 = 0; p2 < 2; p2++) {
                int n_ = wn * 32 + p2 * 16 + (lane & 7) + ((lane >> 4) << 3);
                int kc = kb + (((lane >> 3) & 1) << 3);
                uint32_t off = n_ * 128 + ((((kc >> 3) ^ (n_ & 7))) << 4);
                ldsm4(bhf[p2*4+0], bhf[p2*4+1], bhf[p2*4+2], bhf[p2*4+3], sBh + off);
            }
            #pragma unroll
            for (int i = 0; i < 4; i++) {
                int r_ = wm * 64 + i * 16 + (lane & 7) + (((lane >> 3) & 1) << 3);
                int kc = kb + ((lane >> 4) << 3);
                uint32_t off = r_ * 128 + ((((kc >> 3) ^ (r_ & 7))) << 4);
                uint32_t ahf[4], alf[4];
                ldsm4(ahf[0], ahf[1], ahf[2], ahf[3], sAh + off);
                if (NTERMS >= 2)
                    ldsm4(alf[0], alf[1], alf[2], alf[3], sAl + off);
                #pragma unroll
                for (int j = 0; j < 4; j++) {
                    int bi = (j >> 1) * 4 + (j & 1) * 2;
                    mma_f16(acc[i][j], ahf, bhf[bi], bhf[bi+1]);
                    if (NTERMS >= 2)
                        mma_f16(acc[i][j], alf, bhf[bi], bhf[bi+1]);
                }
            }
        }
        __syncthreads();
    }

    // ---- epilogue ----
    #pragma unroll
    for (int i = 0; i < 4; i++) {
        int r0 = bm + wm * 64 + i * 16 + (lane >> 2);
        #pragma unroll
        for (int j = 0; j < 4; j++) {
            int c0 = bn + wn * 32 + j * 8 + ((lane & 3) << 1);
            epi_store<EPI>(acc[i][j][0], r0,     c0,     M, N, ldc, bias, C, Ch, Cl);
            epi_store<EPI>(acc[i][j][1], r0,     c0 + 1, M, N, ldc, bias, C, Ch, Cl);
            epi_store<EPI>(acc[i][j][2], r0 + 8, c0,     M, N, ldc, bias, C, Ch, Cl);
            epi_store<EPI>(acc[i][j][3], r0 + 8, c0 + 1, M, N, ldc, bias, C, Ch, Cl);
        }
    }
}

// ---------------- round / transpose kernels ---------------------------------
__global__ void round_k(const float4* __restrict__ x, uint4* __restrict__ h,
                        long n8)
{
    long i = (long)blockIdx.x * 256 + threadIdx.x;
    if (i >= n8) return;
    float4 a = x[2 * i], b = x[2 * i + 1];
    float vs[8] = {a.x, a.y, a.z, a.w, b.x, b.y, b.z, b.w};
    f16 hv[8];
    #pragma unroll
    for (int j = 0; j < 8; j++) hv[j] = __float2half_rn(vs[j]);
    h[i] = *(uint4*)hv;
}

// feats [b, l, :DF] (ld 2DF) -> out [b, f, l] hi only
__global__ void splitT_k(const float* __restrict__ x, f16* __restrict__ oh)
{
    __shared__ float t[32][33];
    int b  = blockIdx.z;
    int j0 = blockIdx.y * 32;
    int f0 = blockIdx.x * 32;
    const float* xb = x + (long)b * L_ * 2 * DF;
    int tx = threadIdx.x, ty = threadIdx.y;
    #pragma unroll
    for (int s = 0; s < 32; s += 8) {
        int j = j0 + ty + s, f = f0 + tx;
        t[ty + s][tx] = (f < DF) ? xb[(long)j * 2 * DF + f] : 0.f;
    }
    __syncthreads();
    #pragma unroll
    for (int s = 0; s < 32; s += 8) {
        int f = f0 + ty + s, j = j0 + tx;
        if (f < DF) {
            long o = ((long)b * DF + f) * L_ + j;
            oh[o] = __float2half_rn(t[tx][ty + s]);
        }
    }
}

// ---------------- model-specific small kernels -----------------------------
__global__ void gather_k(const int* __restrict__ tokens,
                         const float* __restrict__ tok_mu,
                         const float* __restrict__ tok_lv,
                         const float* __restrict__ tok_ra,
                         const float* __restrict__ tok_ft,
                         const float* __restrict__ pos_mu,
                         float* __restrict__ mu, float* __restrict__ iv,
                         float* __restrict__ alpha, float* __restrict__ xbuf,
                         f16* __restrict__ xh, f16* __restrict__ xl)
{
    int row = blockIdx.x;
    int l   = row & (L_ - 1);
    int tok = tokens[row];
    for (int d = threadIdx.x; d < DS; d += blockDim.x) {
        mu[row * DS + d] = tok_mu[(long)tok * DS + d] + pos_mu[l * DS + d];
        iv[row * DS + d] = expf(-tok_lv[(long)tok * DS + d]);
    }
    if (threadIdx.x == 0)
        alpha[row] = 1.f / (1.f + expf(-tok_ra[tok]));
    for (int f = threadIdx.x; f < DF; f += blockDim.x) {
        float v = tok_ft[(long)tok * DF + f];
        long o = (long)row * 2 * DF + f;
        xbuf[o] = v;
        split2(v, xh + o, xl + o);
    }
}

__global__ void prep_k(const float* __restrict__ mu, const float* __restrict__ iv,
                       float* __restrict__ mu2,
                       f16* muh, f16* mul_, f16* ivh, f16* ivl)
{
    int row = blockIdx.x;
    int d   = threadIdx.x;            // 128
    float m  = mu[row * DS + d];
    float v  = iv[row * DS + d];
    float miv = m * v;
    split2(m,   muh + row * DS + d,       mul_ + row * DS + d);
    split2(v,   ivh + row * 2 * DS + d,       ivl + row * 2 * DS + d);
    split2(miv, ivh + row * 2 * DS + DS + d,  ivl + row * 2 * DS + DS + d);
    float s = warpSum(m * miv);
    __shared__ float sm[4];
    if ((d & 31) == 0) sm[d >> 5] = s;
    __syncthreads();
    if (d == 0) mu2[row] = sm[0] + sm[1] + sm[2] + sm[3];
}

// mu += tanh(sum of 4 split-K partials + bias)
__global__ void mu_red_k(const float* __restrict__ part,
                         const float* __restrict__ bmu, float* __restrict__ mu)
{
    int i = blockIdx.x * 256 + threadIdx.x;        // BL*DS total
    float s = part[i] + part[i + BL * DS] + part[i + 2 * BL * DS]
            + part[i + 3 * BL * DS] + bmu[i & (DS - 1)];
    mu[i] += tanhf(s);
}

__global__ void __launch_bounds__(512) scan_k(const float* __restrict__ mahal,
                                              const float* __restrict__ alpha,
                                              const float* __restrict__ mu2,
                                              const float* __restrict__ log_tau,
                                              f16* __restrict__ wh)
{
    int row = blockIdx.x;
    int b = row >> 11;
    int l = row & (L_ - 1);
    int j = threadIdx.x;
    float tau = expf(log_tau[0]);
    long off = (long)row * L_ + j;
    float eff = 0.f;
    if (j <= l) {
        float m  = mahal[off] + mu2[b * L_ + j];
        float Kv = expf(-0.5f * m / tau);
        eff = fminf(alpha[b * L_ + j] * Kv, 1.f - 1e-6f);
    }
    float gv = log1pf(-eff);

    int lane = j & 31, warp = j >> 5;
    float incl = gv;
    #pragma unroll
    for (int o = 1; o < 32; o <<= 1) {
        float t = __shfl_up_sync(0xffffffffu, incl, o);
        if (lane >= o) incl += t;
    }
    __shared__ float ws[16];
    if (lane == 31) ws[warp] = incl;
    __syncthreads();
    if (warp == 0) {
        float t = (lane < 16) ? ws[lane] : 0.f;
        #pragma unroll
        for (int o = 1; o < 16; o <<= 1) {
            float u = __shfl_up_sync(0xffffffffu, t, o);
            if (lane >= o) t += u;
        }
        if (lane < 16) ws[lane] = t;
    }
    __syncthreads();
    float prefix = warp ? ws[warp - 1] : 0.f;
    incl += prefix;
    float w = eff * expf(incl - gv);
    wh[off] = __float2half_rn(w);
}

__global__ void ln_k(const float* __restrict__ x, f16* __restrict__ yh,
                     f16* __restrict__ yl,
                     const float* __restrict__ g, const float* __restrict__ b,
                     int n, int ldx, int ldy)
{
    __shared__ float red[32];
    int row = blockIdx.x;
    const float* xr = x + (long)row * ldx;
    float s = 0.f;
    for (int i = threadIdx.x; i < n; i += blockDim.x) s += xr[i];
    s = blockSum(s, red);
    float mean = s / n;
    float v = 0.f;
    for (int i = threadIdx.x; i < n; i += blockDim.x) {
        float d = xr[i] - mean;
        v += d * d;
    }
    v = blockSum(v, red);
    float rstd = rsqrtf(v / n + 1e-5f);
    for (int i = threadIdx.x; i < n; i += blockDim.x) {
        float val = (xr[i] - mean) * rstd * g[i] + b[i];
        long o = (long)row * ldy + i;
        split2(val, yh + o, yl + o);
    }
}

__global__ void alpha_gate_k(const float* __restrict__ x, const float* __restrict__ Wg,
                             const float* __restrict__ bg, float* __restrict__ alpha)
{
    __shared__ float red[32];
    int row = blockIdx.x;
    const float* xr = x + (long)row * 2 * DF;
    float s = 0.f;
    for (int i = threadIdx.x; i < 2 * DF; i += blockDim.x) s += xr[i] * Wg[i];
    s = blockSum(s, red) + bg[0];
    if (threadIdx.x == 0) alpha[row] *= 1.f / (1.f + expf(-s));
}

// ---------------- host side -------------------------------------------------
static void launch_mma(int epi, int terms,
                       const f16* Ah, const f16* Al, const f16* Bh,
                       const float* bias, float* C, f16* Ch, f16* Cl,
                       int M, int N, int K, int ldab, int ldc,
                       long sA1, long sA2, long sB1, long sB2, long sC1, long sC2,
                       int n1, int n2, int flags)
{
    dim3 grid((M + 127) / 128, (N + 127) / 128, n1 * n2);
    #define MARGS Ah, Al, Bh, bias, C, Ch, Cl, M, N, K, ldab, ldc, sA1, sA2, sB1, sB2, sC1, sC2, n2, flags
    switch (epi * 10 + terms) {
        case  1: mma_gemm_k<0, 1><<<grid, 256, SMEM_TOT>>>(MARGS); break;
        case  2: mma_gemm_k<0, 2><<<grid, 256, SMEM_TOT>>>(MARGS); break;
        case 11: mma_gemm_k<1, 1><<<grid, 256, SMEM_TOT>>>(MARGS); break;
        case 32: mma_gemm_k<3, 2><<<grid, 256, SMEM_TOT>>>(MARGS); break;
        case 42: mma_gemm_k<4, 2><<<grid, 256, SMEM_TOT>>>(MARGS); break;
        case 61: mma_gemm_k<6, 1><<<grid, 256, SMEM_TOT>>>(MARGS); break;
        case 72: mma_gemm_k<7, 2><<<grid, 256, SMEM_TOT>>>(MARGS); break;
        case 81: mma_gemm_k<8, 1><<<grid, 256, SMEM_TOT>>>(MARGS); break;
    }
    #undef MARGS
}

static void run_round(const float* x, f16* h, long n) {
    long n8 = n / 8;
    round_k<<<(unsigned)((n8 + 255) / 256), 256>>>((const float4*)x, (uint4*)h, n8);
}

extern "C" void kernel_launch(void* const* d_in, const int* in_sizes, int n_in,
                              void* d_out, int out_size)
{
    const int*   tokens  = (const int*)  d_in[0];
    const float* tok_mu  = (const float*)d_in[1];
    const float* tok_lv  = (const float*)d_in[2];
    const float* tok_ra  = (const float*)d_in[3];
    const float* tok_ft  = (const float*)d_in[4];
    const float* pos_mu  = (const float*)d_in[5];
    const float* log_tau = (const float*)d_in[6];
    const float* Wq      = (const float*)d_in[7];
    const float* bq      = (const float*)d_in[8];
    const float* Whead   = (const float*)d_in[9];
    const float* bhead   = (const float*)d_in[10];
    const float* Wmu     = (const float*)d_in[11];
    const float* bmu     = (const float*)d_in[12];
    const float* Wg      = (const float*)d_in[13];
    const float* bg      = (const float*)d_in[14];
    const float* ln_g    = (const float*)d_in[15];
    const float* ln_b    = (const float*)d_in[16];
    const float* W1      = (const float*)d_in[17];
    const float* b1      = (const float*)d_in[18];
    const float* W2      = (const float*)d_in[19];
    const float* b2      = (const float*)d_in[20];
    const float* lnf_g   = (const float*)d_in[21];
    const float* lnf_b   = (const float*)d_in[22];
    const float* Wlm     = (const float*)d_in[23];
    float* out = (float*)d_out;

    cudaFuncSetAttribute(mma_gemm_k<0,1>, cudaFuncAttributeMaxDynamicSharedMemorySize, SMEM_TOT);
    cudaFuncSetAttribute(mma_gemm_k<0,2>, cudaFuncAttributeMaxDynamicSharedMemorySize, SMEM_TOT);
    cudaFuncSetAttribute(mma_gemm_k<1,1>, cudaFuncAttributeMaxDynamicSharedMemorySize, SMEM_TOT);
    cudaFuncSetAttribute(mma_gemm_k<3,2>, cudaFuncAttributeMaxDynamicSharedMemorySize, SMEM_TOT);
    cudaFuncSetAttribute(mma_gemm_k<4,2>, cudaFuncAttributeMaxDynamicSharedMemorySize, SMEM_TOT);
    cudaFuncSetAttribute(mma_gemm_k<6,1>, cudaFuncAttributeMaxDynamicSharedMemorySize, SMEM_TOT);
    cudaFuncSetAttribute(mma_gemm_k<7,2>, cudaFuncAttributeMaxDynamicSharedMemorySize, SMEM_TOT);
    cudaFuncSetAttribute(mma_gemm_k<8,1>, cudaFuncAttributeMaxDynamicSharedMemorySize, SMEM_TOT);

    float *mu, *iv, *mu2, *alpha, *mahal, *xbuf, *part;
    cudaGetSymbolAddress((void**)&mu,    g_mu);
    cudaGetSymbolAddress((void**)&iv,    g_iv);
    cudaGetSymbolAddress((void**)&mu2,   g_mu2);
    cudaGetSymbolAddress((void**)&alpha, g_alpha);
    cudaGetSymbolAddress((void**)&mahal, g_mahal);
    cudaGetSymbolAddress((void**)&xbuf,  g_xbuf);
    cudaGetSymbolAddress((void**)&part,  g_part);

    f16 *muh, *mul_, *ivh, *ivl, *qeh, *qel, *wh, *fth,
        *mhh, *xh, *xl, *hh, *hl, *h1h, *h1l;
    f16 *wqh, *whdh, *wmuh, *w1h, *w2h, *wlmh;
    cudaGetSymbolAddress((void**)&muh,  g_muh);  cudaGetSymbolAddress((void**)&mul_, g_mul);
    cudaGetSymbolAddress((void**)&ivh,  g_ivh);  cudaGetSymbolAddress((void**)&ivl,  g_ivl);
    cudaGetSymbolAddress((void**)&qeh,  g_qeh);  cudaGetSymbolAddress((void**)&qel,  g_qel);
    cudaGetSymbolAddress((void**)&wh,   g_wh);
    cudaGetSymbolAddress((void**)&fth,  g_fth);
    cudaGetSymbolAddress((void**)&mhh,  g_mhh);
    cudaGetSymbolAddress((void**)&xh,   g_xh);   cudaGetSymbolAddress((void**)&xl,   g_xl);
    cudaGetSymbolAddress((void**)&hh,   g_hh);   cudaGetSymbolAddress((void**)&hl,   g_hl);
    cudaGetSymbolAddress((void**)&h1h,  g_h1h);  cudaGetSymbolAddress((void**)&h1l,  g_h1l);
    cudaGetSymbolAddress((void**)&wqh,  g_wqh);
    cudaGetSymbolAddress((void**)&whdh, g_whdh);
    cudaGetSymbolAddress((void**)&wmuh, g_wmuh);
    cudaGetSymbolAddress((void**)&w1h,  g_w1h);
    cudaGetSymbolAddress((void**)&w2h,  g_w2h);
    cudaGetSymbolAddress((void**)&wlmh, g_wlmh);

    // weight conversions (every call; deterministic) — all single-rounded
    run_round(Wq,    wqh,  (long)512 * DS);
    run_round(Whead, whdh, (long)DF * H_ * DF);
    run_round(Wmu,   wmuh, (long)2 * DS * 2 * DF);
    run_round(W1,    w1h,  (long)2 * 4 * DF * 2 * DF);
    run_round(W2,    w2h,  (long)2 * DF * 4 * DF);
    run_round(Wlm,   wlmh, (long)V_ * DF);

    gather_k<<<BL, 256>>>(tokens, tok_mu, tok_lv, tok_ra, tok_ft, pos_mu,
                          mu, iv, alpha, xbuf, xh, xl);

    for (int p = 0; p < 3; p++) {
        prep_k<<<BL, 128>>>(mu, iv, mu2, muh, mul_, ivh, ivl);

        // q = mu @ Wq^T + bq, packed directly into qe (EPI 7)
        launch_mma(7, 2, muh, mul_, wqh, bq, nullptr, qeh, qel,
                   BL, H_ * DS, DS, DS, 0, 0, 0, 0, 0, 0, 0, 1, 1, 0);

        // mahal (without +mu2): single f16 term (tau-damped), causal-N skip
        launch_mma(0, 1, qeh, qel, ivh, nullptr, mahal, nullptr, nullptr,
                   H_ * L_, L_, 2 * DS, 2 * DS, L_,
                   (long)(H_ * L_) * 2 * DS, 0,
                   (long)L_ * 2 * DS, 0,
                   (long)(H_ * L_) * L_, 0, B_, 1, 1);

        scan_k<<<BHL, 512>>>(mahal, alpha, mu2, log_tau, wh);

        // feats^T hi only
        splitT_k<<<dim3(32, 16, B_), dim3(32, 8)>>>(xbuf, fth);

        // mh = w @ feats^T (causal-K clamp), 1-term, round-out -> mhh
        launch_mma(8, 1, wh, nullptr, fth, nullptr, nullptr, mhh, nullptr,
                   L_, DF, L_, L_, H_ * DF,
                   (long)(H_ * L_) * L_, (long)L_ * L_,
                   (long)DF * L_, 0,
                   (long)L_ * H_ * DF, DF, B_, H_, 2);

        if (p < 2) {
            // meaning = mh @ Whead^T + bhead (1-term) -> xbuf fp32 AND xh/xl (+DF)
            launch_mma(6, 1, mhh, nullptr, whdh, bhead, xbuf + DF, xh + DF, xl + DF,
                       BL, DF, H_ * DF, H_ * DF, 2 * DF,
                       0, 0, 0, 0, 0, 0, 1, 1, 0);

            alpha_gate_k<<<BL, 256>>>(xbuf, Wg + p * 2 * DF, bg + p, alpha);

            // mu-update split-K: partials = x @ Wmu[p]^T (4 K-chunks of 512)
            launch_mma(0, 2, xh, xl, wmuh + (long)p * DS * 2 * DF,
                       nullptr, part, nullptr, nullptr,
                       BL, DS, 512, 2 * DF, DS,
                       0, 512, 0, 512, 0, (long)BL * DS, 1, 4, 4);
            mu_red_k<<<BL * DS / 256, 256>>>(part, bmu + p * DS, mu);

            // h = LN(x) (hi/lo)
            ln_k<<<BL, 256>>>(xbuf, hh, hl, ln_g + p * 2 * DF, ln_b + p * 2 * DF,
                              2 * DF, 2 * DF, 2 * DF);

            // h1 = gelu(h @ W1[p]^T + b1[p]) split-out (2-term)
            launch_mma(3, 2, hh, hl, w1h + (long)p * 4 * DF * 2 * DF,
                       b1 + p * 4 * DF, nullptr, h1h, h1l,
                       BL, 4 * DF, 2 * DF, 2 * DF, 4 * DF,
                       0, 0, 0, 0, 0, 0, 1, 1, 0);

            // feats += h1 @ W2[p]^T + b2[p] : fp32 AND split (2-term)
            launch_mma(4, 2, h1h, h1l, w2h + (long)p * DF * 4 * DF,
                       b2 + p * DF, xbuf, xh, xl,
                       BL, DF, 4 * DF, 4 * DF, 2 * DF,
                       0, 0, 0, 0, 0, 0, 1, 1, 0);
        } else {
            // final-pass meaning: feeds only LN+LM head -> 1-term, fp32 only
            launch_mma(1, 1, mhh, nullptr, whdh, bhead, xbuf + DF,
                       nullptr, nullptr,
                       BL, DF, H_ * DF, H_ * DF, 2 * DF,
                       0, 0, 0, 0, 0, 0, 1, 1, 0);
        }
    }

    // y = LN(meaning); logits = y @ Wlm^T  (1-term: A hi, B hi)
    ln_k<<<BL, 256>>>(xbuf + DF, hh, hl, lnf_g, lnf_b, DF, 2 * DF, DF);
    launch_mma(0, 1, hh, nullptr, wlmh, nullptr, out, nullptr, nullptr,
               BL, V_, DF, DF, V_, 0, 0, 0, 0, 0, 0, 1, 1, 0);
}

// round 15
// speedup vs baseline: 1.3466x; 1.1947x over previous
#include <cuda_runtime.h>
#include <cuda_fp16.h>
#include <math.h>
#include <stdint.h>

#define B_  4
#define L_  512
#define DS  128
#define DF  1000
#define H_  4
#define V_  32000
#define BL  2048    /* B*L   */
#define BHL 8192    /* B*H*L */

typedef __half f16;

// ---------------- fp32 scratch -------------------------------------------
__device__ float g_mu   [BL * DS];
__device__ float g_iv   [BL * DS];
__device__ float g_mu2  [BL];
__device__ float g_alpha[BL];
__device__ float g_mahal[(size_t)BHL * L_];
__device__ float g_xbuf [(size_t)BL * 2 * DF];
__device__ float g_part [4 * BL * DS];          // split-K partials for mu GEMM

// ---------------- fp16 scratch (all single-rounded; no lo buffers) ---------
__device__ f16 g_muh[BL * DS];
__device__ f16 g_ivh[BL * 2 * DS];
__device__ f16 g_qeh[BHL * 2 * DS];
__device__ f16 g_wh [(size_t)BHL * L_];
__device__ f16 g_fth[(size_t)B_ * DF * L_];
__device__ f16 g_mhh[(size_t)BL * H_ * DF];
__device__ f16 g_xh [(size_t)BL * 2 * DF];
__device__ f16 g_hh [(size_t)BL * 2 * DF];
__device__ f16 g_h1h[(size_t)BL * 4 * DF];
// weights
__device__ f16 g_wqh[512 * DS];
__device__ f16 g_whdh[(size_t)DF * H_ * DF];
__device__ f16 g_wmuh[(size_t)2 * DS * 2 * DF];
__device__ f16 g_w1h[(size_t)2 * 4 * DF * 2 * DF];
__device__ f16 g_w2h[(size_t)2 * DF * 4 * DF];
__device__ f16 g_wlmh[(size_t)V_ * DF];

// ---------------- helpers --------------------------------------------------
__device__ __forceinline__ float warpSum(float v) {
    #pragma unroll
    for (int o = 16; o > 0; o >>= 1) v += __shfl_down_sync(0xffffffffu, v, o);
    return v;
}
__device__ float blockSum(float v, float* red) {
    int lane = threadIdx.x & 31, w = threadIdx.x >> 5;
    v = warpSum(v);
    __syncthreads();
    if (lane == 0) red[w] = v;
    __syncthreads();
    if (w == 0) {
        int nw = (blockDim.x + 31) >> 5;
        float t = (lane < nw) ? red[lane] : 0.f;
        t = warpSum(t);
        if (lane == 0) red[0] = t;
    }
    __syncthreads();
    return red[0];
}

// ---------------- mma.sync GEMM engine -------------------------------------
__device__ __forceinline__ void ldsm4(uint32_t& r0, uint32_t& r1, uint32_t& r2,
                                      uint32_t& r3, uint32_t a) {
    asm volatile("ldmatrix.sync.aligned.m8n8.x4.shared.b16 {%0,%1,%2,%3}, [%4];"
                 : "=r"(r0), "=r"(r1), "=r"(r2), "=r"(r3) : "r"(a));
}
__device__ __forceinline__ void mma_f16(float* c, const uint32_t* a,
                                        uint32_t b0, uint32_t b1) {
    asm volatile(
        "mma.sync.aligned.m16n8k16.row.col.f32.f16.f16.f32 "
        "{%0,%1,%2,%3}, {%4,%5,%6,%7}, {%8,%9}, {%0,%1,%2,%3};"
        : "+f"(c[0]), "+f"(c[1]), "+f"(c[2]), "+f"(c[3])
        : "r"(a[0]), "r"(a[1]), "r"(a[2]), "r"(a[3]), "r"(b0), "r"(b1));
}
__device__ __forceinline__ void cpa16(uint32_t dst, const void* src, bool p) {
    asm volatile("cp.async.cg.shared.global [%0], [%1], 16, %2;"
                 :: "r"(dst), "l"(src), "r"(p ? 16 : 0));
}
__device__ __forceinline__ void cpa_commit() {
    asm volatile("cp.async.commit_group;");
}
template<int NN>
__device__ __forceinline__ void cpa_wait() {
    asm volatile("cp.async.wait_group %0;" :: "n"(NN));
}

// EPI: 0 C=v; 1 C=v+bias; 3 Ch=round(gelu(v+bias));
//      4 Cf=C+v+bias fp32, Ch=round(Cf); 6 C=v+bias fp32, Ch=round;
//      7 qe-pack round; 8 Ch=round(v)
template<int EPI>
__device__ __forceinline__ void epi_store(float v, int r, int c, int M, int N,
                                          int ldc, const float* bias, float* C,
                                          f16* Ch) {
    if (r >= M || c >= N) return;
    if (EPI == 1 || EPI == 3 || EPI == 4 || EPI == 6 || EPI == 7) v += bias[c];
    if (EPI == 7) {
        int b = r >> 9, l = r & (L_ - 1), h = c >> 7, d = c & 127;
        long orow = ((long)b * (H_ * L_) + h * L_ + l) * (2 * DS);
        Ch[orow + d]      = __float2half_rn(v * v);
        Ch[orow + DS + d] = __float2half_rn(-2.f * v);
        return;
    }
    long off = (long)r * ldc + c;
    if (EPI == 0 || EPI == 1) C[off] = v;
    else if (EPI == 3) {
        v = 0.5f * v * (1.0f + erff(v * 0.7071067811865476f));
        Ch[off] = __float2half_rn(v);
    } else if (EPI == 4) {
        float nv = C[off] + v;
        C[off] = nv;
        Ch[off] = __float2half_rn(nv);
    } else if (EPI == 6) {
        C[off] = v;
        Ch[off] = __float2half_rn(v);
    } else if (EPI == 8) {
        Ch[off] = __float2half_rn(v);
    }
}

#define KT         64
#define SMEM_STAGE 65536
#define SMEM_TOT   (3 * SMEM_STAGE)

// flags: bit0 = causal N-tile skip (period 512); bit1 = causal K clamp;
//        bit2 = split-K chunk clamp. All GEMMs 1-term (A hi x B hi).
template<int EPI>
__global__ void __launch_bounds__(256) mma_gemm_k(
    const f16* __restrict__ Ah, const f16* __restrict__ Bh,
    const float* __restrict__ bias, float* __restrict__ C,
    f16* __restrict__ Ch,
    int M, int N, int K, int ldab, int ldc,
    long sA1, long sA2, long sB1, long sB2, long sC1, long sC2, int n2,
    int flags)
{
    extern __shared__ __align__(16) unsigned char smem_raw[];
    const uint32_t sbase = (uint32_t)__cvta_generic_to_shared(smem_raw);

    const int bm = blockIdx.x * 128;   // M fast -> better L2 reuse of B stripes
    const int bn = blockIdx.y * 128;

    if ((flags & 1) && bn >= (bm & 511) + 128) return;   // causal skip
    if (flags & 2) { int ke = (bm & 511) + 128; if (ke < K) K = ke; }

    int z  = blockIdx.z;
    int z1 = z / n2, z2 = z - z1 * n2;
    if (flags & 4) { int rem = ldab - z2 * K; if (rem < K) K = rem; }
    Ah += (long)z1 * sA1 + (long)z2 * sA2;
    Bh += (long)z1 * sB1 + (long)z2 * sB2;
    long coff = (long)z1 * sC1 + (long)z2 * sC2;
    if (C)  C  += coff;
    if (Ch) Ch += coff;

    const int tid  = threadIdx.x;
    const int lane = tid & 31;
    const int warp = tid >> 5;
    const int wm = warp >> 2;      // 0..1
    const int wn = warp & 3;       // 0..3
    const int kso = wm << 1;       // ks phase skew across SMSP-paired warps

    float acc[4][4][4];
    #pragma unroll
    for (int i = 0; i < 4; i++)
        #pragma unroll
        for (int j = 0; j < 4; j++)
            #pragma unroll
            for (int e = 0; e < 4; e++) acc[i][j][e] = 0.f;

    const int T = (K + KT - 1) / KT;

    auto load_stage = [&](int st, int kt) {
        const uint32_t sb = sbase + st * SMEM_STAGE;
        const int k0 = kt * KT;
        #pragma unroll
        for (int it = 0; it < 4; it++) {
            int cch = tid + it * 256;            // 0..1023
            int row = cch >> 3, u = cch & 7;
            int gk = k0 + u * 8;
            bool kok = gk < K;
            int gkc = kok ? gk : 0;
            uint32_t sw = row * 128 + ((u ^ (row & 7)) << 4);
            {   // A
                int gm = bm + row;
                bool p = kok && (gm < M);
                long off = (long)(p ? gm : 0) * ldab + gkc;
                cpa16(sb + sw, Ah + off, p);
            }
            {   // B
                int gn = bn + row;
                bool p = kok && (gn < N);
                long off = (long)(p ? gn : 0) * ldab + gkc;
                cpa16(sb + 32768 + sw, Bh + off, p);
            }
        }
    };

    // prologue: stages 0 and 1
    load_stage(0, 0);
    cpa_commit();
    if (1 < T) load_stage(1, 1);
    cpa_commit();

    for (int t = 0; t < T; t++) {
        cpa_wait<1>();
        __syncthreads();

        if (t + 2 < T) load_stage((t + 2) % 3, t + 2);
        cpa_commit();                         // unconditional: keeps group math exact

        const uint32_t sb  = sbase + (t % 3) * SMEM_STAGE;
        const uint32_t sAh = sb, sBh = sb + 32768;

        #pragma unroll
        for (int ksi = 0; ksi < 4; ksi++) {
            const int ks = (ksi + kso) & 3;
            const int kb = ks * 16;
            uint32_t bhf[8];
            #pragma unroll
            for (int p2 = 0; p2 < 2; p2++) {
                int n_ = wn * 32 + p2 * 16 + (lane & 7) + ((lane >> 4) << 3);
                int kc = kb + (((lane >> 3) & 1) << 3);
                uint32_t off = n_ * 128 + ((((kc >> 3) ^ (n_ & 7))) << 4);
                ldsm4(bhf[p2*4+0], bhf[p2*4+1], bhf[p2*4+2], bhf[p2*4+3], sBh + off);
            }
            #pragma unroll
            for (int i = 0; i < 4; i++) {
                int r_ = wm * 64 + i * 16 + (lane & 7) + (((lane >> 3) & 1) << 3);
                int kc = kb + ((lane >> 4) << 3);
                uint32_t off = r_ * 128 + ((((kc >> 3) ^ (r_ & 7))) << 4);
                uint32_t ahf[4];
                ldsm4(ahf[0], ahf[1], ahf[2], ahf[3], sAh + off);
                #pragma unroll
                for (int j = 0; j < 4; j++) {
                    int bi = (j >> 1) * 4 + (j & 1) * 2;
                    mma_f16(acc[i][j], ahf, bhf[bi], bhf[bi+1]);
                }
            }
        }
        __syncthreads();
    }

    // ---- epilogue ----
    #pragma unroll
    for (int i = 0; i < 4; i++) {
        int r0 = bm + wm * 64 + i * 16 + (lane >> 2);
        #pragma unroll
        for (int j = 0; j < 4; j++) {
            int c0 = bn + wn * 32 + j * 8 + ((lane & 3) << 1);
            epi_store<EPI>(acc[i][j][0], r0,     c0,     M, N, ldc, bias, C, Ch);
            epi_store<EPI>(acc[i][j][1], r0,     c0 + 1, M, N, ldc, bias, C, Ch);
            epi_store<EPI>(acc[i][j][2], r0 + 8, c0,     M, N, ldc, bias, C, Ch);
            epi_store<EPI>(acc[i][j][3], r0 + 8, c0 + 1, M, N, ldc, bias, C, Ch);
        }
    }
}

// ---------------- round / transpose kernels ---------------------------------
__global__ void round_k(const float4* __restrict__ x, uint4* __restrict__ h,
                        long n8)
{
    long i = (long)blockIdx.x * 256 + threadIdx.x;
    if (i >= n8) return;
    float4 a = x[2 * i], b = x[2 * i + 1];
    float vs[8] = {a.x, a.y, a.z, a.w, b.x, b.y, b.z, b.w};
    f16 hv[8];
    #pragma unroll
    for (int j = 0; j < 8; j++) hv[j] = __float2half_rn(vs[j]);
    h[i] = *(uint4*)hv;
}

// feats [b, l, :DF] (ld 2DF) -> out [b, f, l]
__global__ void splitT_k(const float* __restrict__ x, f16* __restrict__ oh)
{
    __shared__ float t[32][33];
    int b  = blockIdx.z;
    int j0 = blockIdx.y * 32;
    int f0 = blockIdx.x * 32;
    const float* xb = x + (long)b * L_ * 2 * DF;
    int tx = threadIdx.x, ty = threadIdx.y;
    #pragma unroll
    for (int s = 0; s < 32; s += 8) {
        int j = j0 + ty + s, f = f0 + tx;
        t[ty + s][tx] = (f < DF) ? xb[(long)j * 2 * DF + f] : 0.f;
    }
    __syncthreads();
    #pragma unroll
    for (int s = 0; s < 32; s += 8) {
        int f = f0 + ty + s, j = j0 + tx;
        if (f < DF) {
            long o = ((long)b * DF + f) * L_ + j;
            oh[o] = __float2half_rn(t[tx][ty + s]);
        }
    }
}

// ---------------- model-specific small kernels -----------------------------
__global__ void gather_k(const int* __restrict__ tokens,
                         const float* __restrict__ tok_mu,
                         const float* __restrict__ tok_lv,
                         const float* __restrict__ tok_ra,
                         const float* __restrict__ tok_ft,
                         const float* __restrict__ pos_mu,
                         float* __restrict__ mu, float* __restrict__ iv,
                         float* __restrict__ alpha, float* __restrict__ xbuf,
                         f16* __restrict__ xh)
{
    int row = blockIdx.x;
    int l   = row & (L_ - 1);
    int tok = tokens[row];
    for (int d = threadIdx.x; d < DS; d += blockDim.x) {
        mu[row * DS + d] = tok_mu[(long)tok * DS + d] + pos_mu[l * DS + d];
        iv[row * DS + d] = expf(-tok_lv[(long)tok * DS + d]);
    }
    if (threadIdx.x == 0)
        alpha[row] = 1.f / (1.f + expf(-tok_ra[tok]));
    for (int f = threadIdx.x; f < DF; f += blockDim.x) {
        float v = tok_ft[(long)tok * DF + f];
        long o = (long)row * 2 * DF + f;
        xbuf[o] = v;
        xh[o] = __float2half_rn(v);
    }
}

__global__ void prep_k(const float* __restrict__ mu, const float* __restrict__ iv,
                       float* __restrict__ mu2,
                       f16* muh, f16* ivh)
{
    int row = blockIdx.x;
    int d   = threadIdx.x;            // 128
    float m  = mu[row * DS + d];
    float v  = iv[row * DS + d];
    float miv = m * v;
    muh[row * DS + d]           = __float2half_rn(m);
    ivh[row * 2 * DS + d]       = __float2half_rn(v);
    ivh[row * 2 * DS + DS + d]  = __float2half_rn(miv);
    float s = warpSum(m * miv);
    __shared__ float sm[4];
    if ((d & 31) == 0) sm[d >> 5] = s;
    __syncthreads();
    if (d == 0) mu2[row] = sm[0] + sm[1] + sm[2] + sm[3];
}

// mu += tanh(sum of 4 split-K partials + bias)
__global__ void mu_red_k(const float* __restrict__ part,
                         const float* __restrict__ bmu, float* __restrict__ mu)
{
    int i = blockIdx.x * 256 + threadIdx.x;        // BL*DS total
    float s = part[i] + part[i + BL * DS] + part[i + 2 * BL * DS]
            + part[i + 3 * BL * DS] + bmu[i & (DS - 1)];
    mu[i] += tanhf(s);
}

__global__ void __launch_bounds__(512) scan_k(const float* __restrict__ mahal,
                                              const float* __restrict__ alpha,
                                              const float* __restrict__ mu2,
                                              const float* __restrict__ log_tau,
                                              f16* __restrict__ wh)
{
    int row = blockIdx.x;
    int b = row >> 11;
    int l = row & (L_ - 1);
    int j = threadIdx.x;
    float tau = expf(log_tau[0]);
    long off = (long)row * L_ + j;
    float eff = 0.f;
    if (j <= l) {
        float m  = mahal[off] + mu2[b * L_ + j];
        float Kv = expf(-0.5f * m / tau);
        eff = fminf(alpha[b * L_ + j] * Kv, 1.f - 1e-6f);
    }
    float gv = log1pf(-eff);

    int lane = j & 31, warp = j >> 5;
    float incl = gv;
    #pragma unroll
    for (int o = 1; o < 32; o <<= 1) {
        float t = __shfl_up_sync(0xffffffffu, incl, o);
        if (lane >= o) incl += t;
    }
    __shared__ float ws[16];
    if (lane == 31) ws[warp] = incl;
    __syncthreads();
    if (warp == 0) {
        float t = (lane < 16) ? ws[lane] : 0.f;
        #pragma unroll
        for (int o = 1; o < 16; o <<= 1) {
            float u = __shfl_up_sync(0xffffffffu, t, o);
            if (lane >= o) t += u;
        }
        if (lane < 16) ws[lane] = t;
    }
    __syncthreads();
    float prefix = warp ? ws[warp - 1] : 0.f;
    incl += prefix;
    float w = eff * expf(incl - gv);
    wh[off] = __float2half_rn(w);
}

__global__ void ln_k(const float* __restrict__ x, f16* __restrict__ yh,
                     const float* __restrict__ g, const float* __restrict__ b,
                     int n, int ldx, int ldy)
{
    __shared__ float red[32];
    int row = blockIdx.x;
    const float* xr = x + (long)row * ldx;
    float s = 0.f;
    for (int i = threadIdx.x; i < n; i += blockDim.x) s += xr[i];
    s = blockSum(s, red);
    float mean = s / n;
    float v = 0.f;
    for (int i = threadIdx.x; i < n; i += blockDim.x) {
        float d = xr[i] - mean;
        v += d * d;
    }
    v = blockSum(v, red);
    float rstd = rsqrtf(v / n + 1e-5f);
    for (int i = threadIdx.x; i < n; i += blockDim.x) {
        float val = (xr[i] - mean) * rstd * g[i] + b[i];
        yh[(long)row * ldy + i] = __float2half_rn(val);
    }
}

__global__ void alpha_gate_k(const float* __restrict__ x, const float* __restrict__ Wg,
                             const float* __restrict__ bg, float* __restrict__ alpha)
{
    __shared__ float red[32];
    int row = blockIdx.x;
    const float* xr = x + (long)row * 2 * DF;
    float s = 0.f;
    for (int i = threadIdx.x; i < 2 * DF; i += blockDim.x) s += xr[i] * Wg[i];
    s = blockSum(s, red) + bg[0];
    if (threadIdx.x == 0) alpha[row] *= 1.f / (1.f + expf(-s));
}

// ---------------- host side -------------------------------------------------
static void launch_mma(int epi,
                       const f16* Ah, const f16* Bh,
                       const float* bias, float* C, f16* Ch,
                       int M, int N, int K, int ldab, int ldc,
                       long sA1, long sA2, long sB1, long sB2, long sC1, long sC2,
                       int n1, int n2, int flags)
{
    dim3 grid((M + 127) / 128, (N + 127) / 128, n1 * n2);
    #define MARGS Ah, Bh, bias, C, Ch, M, N, K, ldab, ldc, sA1, sA2, sB1, sB2, sC1, sC2, n2, flags
    switch (epi) {
        case 0: mma_gemm_k<0><<<grid, 256, SMEM_TOT>>>(MARGS); break;
        case 1: mma_gemm_k<1><<<grid, 256, SMEM_TOT>>>(MARGS); break;
        case 3: mma_gemm_k<3><<<grid, 256, SMEM_TOT>>>(MARGS); break;
        case 4: mma_gemm_k<4><<<grid, 256, SMEM_TOT>>>(MARGS); break;
        case 6: mma_gemm_k<6><<<grid, 256, SMEM_TOT>>>(MARGS); break;
        case 7: mma_gemm_k<7><<<grid, 256, SMEM_TOT>>>(MARGS); break;
        case 8: mma_gemm_k<8><<<grid, 256, SMEM_TOT>>>(MARGS); break;
    }
    #undef MARGS
}

static void run_round(const float* x, f16* h, long n) {
    long n8 = n / 8;
    round_k<<<(unsigned)((n8 + 255) / 256), 256>>>((const float4*)x, (uint4*)h, n8);
}

extern "C" void kernel_launch(void* const* d_in, const int* in_sizes, int n_in,
                              void* d_out, int out_size)
{
    const int*   tokens  = (const int*)  d_in[0];
    const float* tok_mu  = (const float*)d_in[1];
    const float* tok_lv  = (const float*)d_in[2];
    const float* tok_ra  = (const float*)d_in[3];
    const float* tok_ft  = (const float*)d_in[4];
    const float* pos_mu  = (const float*)d_in[5];
    const float* log_tau = (const float*)d_in[6];
    const float* Wq      = (const float*)d_in[7];
    const float* bq      = (const float*)d_in[8];
    const float* Whead   = (const float*)d_in[9];
    const float* bhead   = (const float*)d_in[10];
    const float* Wmu     = (const float*)d_in[11];
    const float* bmu     = (const float*)d_in[12];
    const float* Wg      = (const float*)d_in[13];
    const float* bg      = (const float*)d_in[14];
    const float* ln_g    = (const float*)d_in[15];
    const float* ln_b    = (const float*)d_in[16];
    const float* W1      = (const float*)d_in[17];
    const float* b1      = (const float*)d_in[18];
    const float* W2      = (const float*)d_in[19];
    const float* b2      = (const float*)d_in[20];
    const float* lnf_g   = (const float*)d_in[21];
    const float* lnf_b   = (const float*)d_in[22];
    const float* Wlm     = (const float*)d_in[23];
    float* out = (float*)d_out;

    cudaFuncSetAttribute(mma_gemm_k<0>, cudaFuncAttributeMaxDynamicSharedMemorySize, SMEM_TOT);
    cudaFuncSetAttribute(mma_gemm_k<1>, cudaFuncAttributeMaxDynamicSharedMemorySize, SMEM_TOT);
    cudaFuncSetAttribute(mma_gemm_k<3>, cudaFuncAttributeMaxDynamicSharedMemorySize, SMEM_TOT);
    cudaFuncSetAttribute(mma_gemm_k<4>, cudaFuncAttributeMaxDynamicSharedMemorySize, SMEM_TOT);
    cudaFuncSetAttribute(mma_gemm_k<6>, cudaFuncAttributeMaxDynamicSharedMemorySize, SMEM_TOT);
    cudaFuncSetAttribute(mma_gemm_k<7>, cudaFuncAttributeMaxDynamicSharedMemorySize, SMEM_TOT);
    cudaFuncSetAttribute(mma_gemm_k<8>, cudaFuncAttributeMaxDynamicSharedMemorySize, SMEM_TOT);

    float *mu, *iv, *mu2, *alpha, *mahal, *xbuf, *part;
    cudaGetSymbolAddress((void**)&mu,    g_mu);
    cudaGetSymbolAddress((void**)&iv,    g_iv);
    cudaGetSymbolAddress((void**)&mu2,   g_mu2);
    cudaGetSymbolAddress((void**)&alpha, g_alpha);
    cudaGetSymbolAddress((void**)&mahal, g_mahal);
    cudaGetSymbolAddress((void**)&xbuf,  g_xbuf);
    cudaGetSymbolAddress((void**)&part,  g_part);

    f16 *muh, *ivh, *qeh, *wh, *fth, *mhh, *xh, *hh, *h1h;
    f16 *wqh, *whdh, *wmuh, *w1h, *w2h, *wlmh;
    cudaGetSymbolAddress((void**)&muh,  g_muh);
    cudaGetSymbolAddress((void**)&ivh,  g_ivh);
    cudaGetSymbolAddress((void**)&qeh,  g_qeh);
    cudaGetSymbolAddress((void**)&wh,   g_wh);
    cudaGetSymbolAddress((void**)&fth,  g_fth);
    cudaGetSymbolAddress((void**)&mhh,  g_mhh);
    cudaGetSymbolAddress((void**)&xh,   g_xh);
    cudaGetSymbolAddress((void**)&hh,   g_hh);
    cudaGetSymbolAddress((void**)&h1h,  g_h1h);
    cudaGetSymbolAddress((void**)&wqh,  g_wqh);
    cudaGetSymbolAddress((void**)&whdh, g_whdh);
    cudaGetSymbolAddress((void**)&wmuh, g_wmuh);
    cudaGetSymbolAddress((void**)&w1h,  g_w1h);
    cudaGetSymbolAddress((void**)&w2h,  g_w2h);
    cudaGetSymbolAddress((void**)&wlmh, g_wlmh);

    // weight conversions (every call; deterministic)
    run_round(Wq,    wqh,  (long)512 * DS);
    run_round(Whead, whdh, (long)DF * H_ * DF);
    run_round(Wmu,   wmuh, (long)2 * DS * 2 * DF);
    run_round(W1,    w1h,  (long)2 * 4 * DF * 2 * DF);
    run_round(W2,    w2h,  (long)2 * DF * 4 * DF);
    run_round(Wlm,   wlmh, (long)V_ * DF);

    gather_k<<<BL, 256>>>(tokens, tok_mu, tok_lv, tok_ra, tok_ft, pos_mu,
                          mu, iv, alpha, xbuf, xh);

    for (int p = 0; p < 3; p++) {
        prep_k<<<BL, 128>>>(mu, iv, mu2, muh, ivh);

        // q = mu @ Wq^T + bq, packed directly into qe (EPI 7)
        launch_mma(7, muh, wqh, bq, nullptr, qeh,
                   BL, H_ * DS, DS, DS, 0, 0, 0, 0, 0, 0, 0, 1, 1, 0);

        // mahal (without +mu2): tau-damped, causal-N skip
        launch_mma(0, qeh, ivh, nullptr, mahal, nullptr,
                   H_ * L_, L_, 2 * DS, 2 * DS, L_,
                   (long)(H_ * L_) * 2 * DS, 0,
                   (long)L_ * 2 * DS, 0,
                   (long)(H_ * L_) * L_, 0, B_, 1, 1);

        scan_k<<<BHL, 512>>>(mahal, alpha, mu2, log_tau, wh);

        // feats^T
        splitT_k<<<dim3(32, 16, B_), dim3(32, 8)>>>(xbuf, fth);

        // mh = w @ feats^T (causal-K clamp), round-out -> mhh
        launch_mma(8, wh, fth, nullptr, nullptr, mhh,
                   L_, DF, L_, L_, H_ * DF,
                   (long)(H_ * L_) * L_, (long)L_ * L_,
                   (long)DF * L_, 0,
                   (long)L_ * H_ * DF, DF, B_, H_, 2);

        if (p < 2) {
            // meaning = mh @ Whead^T + bhead -> xbuf fp32 AND xh (+DF)
            launch_mma(6, mhh, whdh, bhead, xbuf + DF, xh + DF,
                       BL, DF, H_ * DF, H_ * DF, 2 * DF,
                       0, 0, 0, 0, 0, 0, 1, 1, 0);

            alpha_gate_k<<<BL, 256>>>(xbuf, Wg + p * 2 * DF, bg + p, alpha);

            // mu-update split-K: partials = x @ Wmu[p]^T (4 K-chunks of 512)
            launch_mma(0, xh, wmuh + (long)p * DS * 2 * DF,
                       nullptr, part, nullptr,
                       BL, DS, 512, 2 * DF, DS,
                       0, 512, 0, 512, 0, (long)BL * DS, 1, 4, 4);
            mu_red_k<<<BL * DS / 256, 256>>>(part, bmu + p * DS, mu);

            // h = LN(x)
            ln_k<<<BL, 256>>>(xbuf, hh, ln_g + p * 2 * DF, ln_b + p * 2 * DF,
                              2 * DF, 2 * DF, 2 * DF);

            // h1 = gelu(h @ W1[p]^T + b1[p]) round-out
            launch_mma(3, hh, w1h + (long)p * 4 * DF * 2 * DF,
                       b1 + p * 4 * DF, nullptr, h1h,
                       BL, 4 * DF, 2 * DF, 2 * DF, 4 * DF,
                       0, 0, 0, 0, 0, 0, 1, 1, 0);

            // feats += h1 @ W2[p]^T + b2[p] : fp32 AND round into xh
            launch_mma(4, h1h, w2h + (long)p * DF * 4 * DF,
                       b2 + p * DF, xbuf, xh,
                       BL, DF, 4 * DF, 4 * DF, 2 * DF,
                       0, 0, 0, 0, 0, 0, 1, 1, 0);
        } else {
            // final-pass meaning: feeds only LN+LM head -> fp32 only
            launch_mma(1, mhh, whdh, bhead, xbuf + DF, nullptr,
                       BL, DF, H_ * DF, H_ * DF, 2 * DF,
                       0, 0, 0, 0, 0, 0, 1, 1, 0);
        }
    }

    // y = LN(meaning); logits = y @ Wlm^T
    ln_k<<<BL, 256>>>(xbuf + DF, hh, lnf_g, lnf_b, DF, 2 * DF, DF);
    launch_mma(0, hh, wlmh, nullptr, out, nullptr,
               BL, V_, DF, DF, V_, 0, 0, 0, 0, 0, 0, 1, 1, 0);
}

// round 16
// speedup vs baseline: 1.5115x; 1.1224x over previous
#include <cuda_runtime.h>
#include <cuda_fp16.h>
#include <math.h>
#include <stdint.h>

#define B_  4
#define L_  512
#define DS  128
#define DF  1000
#define H_  4
#define V_  32000
#define BL  2048    /* B*L   */
#define BHL 8192    /* B*H*L */

typedef __half f16;

// ---------------- fp32 scratch -------------------------------------------
__device__ float g_mu   [BL * DS];
__device__ float g_iv   [BL * DS];
__device__ float g_mu2  [BL];
__device__ float g_alpha[BL];
__device__ float g_mahal[(size_t)BHL * L_];
__device__ float g_xbuf [(size_t)BL * 2 * DF];
__device__ float g_part [4 * BL * DS];          // split-K partials for mu GEMM

// ---------------- fp16 scratch (all single-rounded) -------------------------
__device__ f16 g_muh[BL * DS];
__device__ f16 g_ivh[BL * 2 * DS];
__device__ f16 g_qeh[BHL * 2 * DS];
__device__ f16 g_wh [(size_t)BHL * L_];
__device__ f16 g_fth[(size_t)B_ * DF * L_];
__device__ f16 g_mhh[(size_t)BL * H_ * DF];
__device__ f16 g_xh [(size_t)BL * 2 * DF];
__device__ f16 g_hh [(size_t)BL * 2 * DF];
__device__ f16 g_h1h[(size_t)BL * 4 * DF];
// weights
__device__ f16 g_wqh[512 * DS];
__device__ f16 g_whdh[(size_t)DF * H_ * DF];
__device__ f16 g_wmuh[(size_t)2 * DS * 2 * DF];
__device__ f16 g_w1h[(size_t)2 * 4 * DF * 2 * DF];
__device__ f16 g_w2h[(size_t)2 * DF * 4 * DF];
__device__ f16 g_wlmh[(size_t)V_ * DF];

// ---------------- helpers --------------------------------------------------
__device__ __forceinline__ float warpSum(float v) {
    #pragma unroll
    for (int o = 16; o > 0; o >>= 1) v += __shfl_down_sync(0xffffffffu, v, o);
    return v;
}
__device__ float blockSum(float v, float* red) {
    int lane = threadIdx.x & 31, w = threadIdx.x >> 5;
    v = warpSum(v);
    __syncthreads();
    if (lane == 0) red[w] = v;
    __syncthreads();
    if (w == 0) {
        int nw = (blockDim.x + 31) >> 5;
        float t = (lane < nw) ? red[lane] : 0.f;
        t = warpSum(t);
        if (lane == 0) red[0] = t;
    }
    __syncthreads();
    return red[0];
}

// ---------------- mma.sync GEMM engine -------------------------------------
__device__ __forceinline__ void ldsm4(uint32_t& r0, uint32_t& r1, uint32_t& r2,
                                      uint32_t& r3, uint32_t a) {
    asm volatile("ldmatrix.sync.aligned.m8n8.x4.shared.b16 {%0,%1,%2,%3}, [%4];"
                 : "=r"(r0), "=r"(r1), "=r"(r2), "=r"(r3) : "r"(a));
}
__device__ __forceinline__ void mma_f16(float* c, const uint32_t* a,
                                        uint32_t b0, uint32_t b1) {
    asm volatile(
        "mma.sync.aligned.m16n8k16.row.col.f32.f16.f16.f32 "
        "{%0,%1,%2,%3}, {%4,%5,%6,%7}, {%8,%9}, {%0,%1,%2,%3};"
        : "+f"(c[0]), "+f"(c[1]), "+f"(c[2]), "+f"(c[3])
        : "r"(a[0]), "r"(a[1]), "r"(a[2]), "r"(a[3]), "r"(b0), "r"(b1));
}
__device__ __forceinline__ void cpa16(uint32_t dst, const void* src, bool p) {
    asm volatile("cp.async.cg.shared.global [%0], [%1], 16, %2;"
                 :: "r"(dst), "l"(src), "r"(p ? 16 : 0));
}
__device__ __forceinline__ void cpa_commit() {
    asm volatile("cp.async.commit_group;");
}
template<int NN>
__device__ __forceinline__ void cpa_wait() {
    asm volatile("cp.async.wait_group %0;" :: "n"(NN));
}

// EPI: 0 C=v; 1 C=v+bias; 3 Ch=round(gelu(v+bias));
//      4 Cf=C+v+bias fp32, Ch=round(Cf); 6 C=v+bias fp32, Ch=round;
//      7 qe-pack round; 8 Ch=round(v)
template<int EPI>
__device__ __forceinline__ void epi_store(float v, int r, int c, int M, int N,
                                          int ldc, const float* bias, float* C,
                                          f16* Ch) {
    if (r >= M || c >= N) return;
    if (EPI == 1 || EPI == 3 || EPI == 4 || EPI == 6 || EPI == 7) v += bias[c];
    if (EPI == 7) {
        int b = r >> 9, l = r & (L_ - 1), h = c >> 7, d = c & 127;
        long orow = ((long)b * (H_ * L_) + h * L_ + l) * (2 * DS);
        Ch[orow + d]      = __float2half_rn(v * v);
        Ch[orow + DS + d] = __float2half_rn(-2.f * v);
        return;
    }
    long off = (long)r * ldc + c;
    if (EPI == 0 || EPI == 1) C[off] = v;
    else if (EPI == 3) {
        v = 0.5f * v * (1.0f + erff(v * 0.7071067811865476f));
        Ch[off] = __float2half_rn(v);
    } else if (EPI == 4) {
        float nv = C[off] + v;
        C[off] = nv;
        Ch[off] = __float2half_rn(nv);
    } else if (EPI == 6) {
        C[off] = v;
        Ch[off] = __float2half_rn(v);
    } else if (EPI == 8) {
        Ch[off] = __float2half_rn(v);
    }
}

#define KT         64
#define SMEM_STAGE 32768      /* A 16K | B 16K  (1-term layout) */
#define SMEM_TOT   (3 * SMEM_STAGE)   /* 96 KB -> 2 CTAs/SM */

// flags: bit0 = causal N-tile skip (period 512); bit1 = causal K clamp;
//        bit2 = split-K chunk clamp. All GEMMs 1-term (A hi x B hi).
template<int EPI>
__global__ void __launch_bounds__(256, 2) mma_gemm_k(
    const f16* __restrict__ Ah, const f16* __restrict__ Bh,
    const float* __restrict__ bias, float* __restrict__ C,
    f16* __restrict__ Ch,
    int M, int N, int K, int ldab, int ldc,
    long sA1, long sA2, long sB1, long sB2, long sC1, long sC2, int n2,
    int flags)
{
    extern __shared__ __align__(16) unsigned char smem_raw[];
    const uint32_t sbase = (uint32_t)__cvta_generic_to_shared(smem_raw);

    const int bm = blockIdx.x * 128;   // M fast -> better L2 reuse of B stripes
    const int bn = blockIdx.y * 128;

    if ((flags & 1) && bn >= (bm & 511) + 128) return;   // causal skip
    if (flags & 2) { int ke = (bm & 511) + 128; if (ke < K) K = ke; }

    int z  = blockIdx.z;
    int z1 = z / n2, z2 = z - z1 * n2;
    if (flags & 4) { int rem = ldab - z2 * K; if (rem < K) K = rem; }
    Ah += (long)z1 * sA1 + (long)z2 * sA2;
    Bh += (long)z1 * sB1 + (long)z2 * sB2;
    long coff = (long)z1 * sC1 + (long)z2 * sC2;
    if (C)  C  += coff;
    if (Ch) Ch += coff;

    const int tid  = threadIdx.x;
    const int lane = tid & 31;
    const int warp = tid >> 5;
    const int wm = warp >> 2;      // 0..1
    const int wn = warp & 3;       // 0..3
    const int kso = wm << 1;       // ks phase skew across SMSP-paired warps

    float acc[4][4][4];
    #pragma unroll
    for (int i = 0; i < 4; i++)
        #pragma unroll
        for (int j = 0; j < 4; j++)
            #pragma unroll
            for (int e = 0; e < 4; e++) acc[i][j][e] = 0.f;

    const int T = (K + KT - 1) / KT;

    auto load_stage = [&](int st, int kt) {
        const uint32_t sb = sbase + st * SMEM_STAGE;
        const int k0 = kt * KT;
        #pragma unroll
        for (int it = 0; it < 4; it++) {
            int cch = tid + it * 256;            // 0..1023
            int row = cch >> 3, u = cch & 7;
            int gk = k0 + u * 8;
            bool kok = gk < K;
            int gkc = kok ? gk : 0;
            uint32_t sw = row * 128 + ((u ^ (row & 7)) << 4);
            {   // A
                int gm = bm + row;
                bool p = kok && (gm < M);
                long off = (long)(p ? gm : 0) * ldab + gkc;
                cpa16(sb + sw, Ah + off, p);
            }
            {   // B
                int gn = bn + row;
                bool p = kok && (gn < N);
                long off = (long)(p ? gn : 0) * ldab + gkc;
                cpa16(sb + 16384 + sw, Bh + off, p);
            }
        }
    };

    // prologue: stages 0 and 1
    load_stage(0, 0);
    cpa_commit();
    if (1 < T) load_stage(1, 1);
    cpa_commit();

    for (int t = 0; t < T; t++) {
        cpa_wait<1>();
        __syncthreads();

        if (t + 2 < T) load_stage((t + 2) % 3, t + 2);
        cpa_commit();                         // unconditional: keeps group math exact

        const uint32_t sb  = sbase + (t % 3) * SMEM_STAGE;
        const uint32_t sAh = sb, sBh = sb + 16384;

        #pragma unroll
        for (int ksi = 0; ksi < 4; ksi++) {
            const int ks = (ksi + kso) & 3;
            const int kb = ks * 16;
            uint32_t bhf[8];
            #pragma unroll
            for (int p2 = 0; p2 < 2; p2++) {
                int n_ = wn * 32 + p2 * 16 + (lane & 7) + ((lane >> 4) << 3);
                int kc = kb + (((lane >> 3) & 1) << 3);
                uint32_t off = n_ * 128 + ((((kc >> 3) ^ (n_ & 7))) << 4);
                ldsm4(bhf[p2*4+0], bhf[p2*4+1], bhf[p2*4+2], bhf[p2*4+3], sBh + off);
            }
            #pragma unroll
            for (int i = 0; i < 4; i++) {
                int r_ = wm * 64 + i * 16 + (lane & 7) + (((lane >> 3) & 1) << 3);
                int kc = kb + ((lane >> 4) << 3);
                uint32_t off = r_ * 128 + ((((kc >> 3) ^ (r_ & 7))) << 4);
                uint32_t ahf[4];
                ldsm4(ahf[0], ahf[1], ahf[2], ahf[3], sAh + off);
                #pragma unroll
                for (int j = 0; j < 4; j++) {
                    int bi = (j >> 1) * 4 + (j & 1) * 2;
                    mma_f16(acc[i][j], ahf, bhf[bi], bhf[bi+1]);
                }
            }
        }
        __syncthreads();
    }

    // ---- epilogue ----
    #pragma unroll
    for (int i = 0; i < 4; i++) {
        int r0 = bm + wm * 64 + i * 16 + (lane >> 2);
        #pragma unroll
        for (int j = 0; j < 4; j++) {
            int c0 = bn + wn * 32 + j * 8 + ((lane & 3) << 1);
            epi_store<EPI>(acc[i][j][0], r0,     c0,     M, N, ldc, bias, C, Ch);
            epi_store<EPI>(acc[i][j][1], r0,     c0 + 1, M, N, ldc, bias, C, Ch);
            epi_store<EPI>(acc[i][j][2], r0 + 8, c0,     M, N, ldc, bias, C, Ch);
            epi_store<EPI>(acc[i][j][3], r0 + 8, c0 + 1, M, N, ldc, bias, C, Ch);
        }
    }
}

// ---------------- round / transpose kernels ---------------------------------
__global__ void round_k(const float4* __restrict__ x, uint4* __restrict__ h,
                        long n8)
{
    long i = (long)blockIdx.x * 256 + threadIdx.x;
    if (i >= n8) return;
    float4 a = x[2 * i], b = x[2 * i + 1];
    float vs[8] = {a.x, a.y, a.z, a.w, b.x, b.y, b.z, b.w};
    f16 hv[8];
    #pragma unroll
    for (int j = 0; j < 8; j++) hv[j] = __float2half_rn(vs[j]);
    h[i] = *(uint4*)hv;
}

// feats [b, l, :DF] (ld 2DF) -> out [b, f, l]
__global__ void splitT_k(const float* __restrict__ x, f16* __restrict__ oh)
{
    __shared__ float t[32][33];
    int b  = blockIdx.z;
    int j0 = blockIdx.y * 32;
    int f0 = blockIdx.x * 32;
    const float* xb = x + (long)b * L_ * 2 * DF;
    int tx = threadIdx.x, ty = threadIdx.y;
    #pragma unroll
    for (int s = 0; s < 32; s += 8) {
        int j = j0 + ty + s, f = f0 + tx;
        t[ty + s][tx] = (f < DF) ? xb[(long)j * 2 * DF + f] : 0.f;
    }
    __syncthreads();
    #pragma unroll
    for (int s = 0; s < 32; s += 8) {
        int f = f0 + ty + s, j = j0 + tx;
        if (f < DF) {
            long o = ((long)b * DF + f) * L_ + j;
            oh[o] = __float2half_rn(t[tx][ty + s]);
        }
    }
}

// ---------------- model-specific small kernels -----------------------------
__global__ void gather_k(const int* __restrict__ tokens,
                         const float* __restrict__ tok_mu,
                         const float* __restrict__ tok_lv,
                         const float* __restrict__ tok_ra,
                         const float* __restrict__ tok_ft,
                         const float* __restrict__ pos_mu,
                         float* __restrict__ mu, float* __restrict__ iv,
                         float* __restrict__ alpha, float* __restrict__ xbuf,
                         f16* __restrict__ xh)
{
    int row = blockIdx.x;
    int l   = row & (L_ - 1);
    int tok = tokens[row];
    for (int d = threadIdx.x; d < DS; d += blockDim.x) {
        mu[row * DS + d] = tok_mu[(long)tok * DS + d] + pos_mu[l * DS + d];
        iv[row * DS + d] = expf(-tok_lv[(long)tok * DS + d]);
    }
    if (threadIdx.x == 0)
        alpha[row] = 1.f / (1.f + expf(-tok_ra[tok]));
    for (int f = threadIdx.x; f < DF; f += blockDim.x) {
        float v = tok_ft[(long)tok * DF + f];
        long o = (long)row * 2 * DF + f;
        xbuf[o] = v;
        xh[o] = __float2half_rn(v);
    }
}

__global__ void prep_k(const float* __restrict__ mu, const float* __restrict__ iv,
                       float* __restrict__ mu2,
                       f16* muh, f16* ivh)
{
    int row = blockIdx.x;
    int d   = threadIdx.x;            // 128
    float m  = mu[row * DS + d];
    float v  = iv[row * DS + d];
    float miv = m * v;
    muh[row * DS + d]           = __float2half_rn(m);
    ivh[row * 2 * DS + d]       = __float2half_rn(v);
    ivh[row * 2 * DS + DS + d]  = __float2half_rn(miv);
    float s = warpSum(m * miv);
    __shared__ float sm[4];
    if ((d & 31) == 0) sm[d >> 5] = s;
    __syncthreads();
    if (d == 0) mu2[row] = sm[0] + sm[1] + sm[2] + sm[3];
}

// mu += tanh(sum of 4 split-K partials + bias)
__global__ void mu_red_k(const float* __restrict__ part,
                         const float* __restrict__ bmu, float* __restrict__ mu)
{
    int i = blockIdx.x * 256 + threadIdx.x;        // BL*DS total
    float s = part[i] + part[i + BL * DS] + part[i + 2 * BL * DS]
            + part[i + 3 * BL * DS] + bmu[i & (DS - 1)];
    mu[i] += tanhf(s);
}

__global__ void __launch_bounds__(512) scan_k(const float* __restrict__ mahal,
                                              const float* __restrict__ alpha,
                                              const float* __restrict__ mu2,
                                              const float* __restrict__ log_tau,
                                              f16* __restrict__ wh)
{
    int row = blockIdx.x;
    int b = row >> 11;
    int l = row & (L_ - 1);
    int j = threadIdx.x;
    float tau = expf(log_tau[0]);
    long off = (long)row * L_ + j;
    float eff = 0.f;
    if (j <= l) {
        float m  = mahal[off] + mu2[b * L_ + j];
        float Kv = expf(-0.5f * m / tau);
        eff = fminf(alpha[b * L_ + j] * Kv, 1.f - 1e-6f);
    }
    float gv = log1pf(-eff);

    int lane = j & 31, warp = j >> 5;
    float incl = gv;
    #pragma unroll
    for (int o = 1; o < 32; o <<= 1) {
        float t = __shfl_up_sync(0xffffffffu, incl, o);
        if (lane >= o) incl += t;
    }
    __shared__ float ws[16];
    if (lane == 31) ws[warp] = incl;
    __syncthreads();
    if (warp == 0) {
        float t = (lane < 16) ? ws[lane] : 0.f;
        #pragma unroll
        for (int o = 1; o < 16; o <<= 1) {
            float u = __shfl_up_sync(0xffffffffu, t, o);
            if (lane >= o) t += u;
        }
        if (lane < 16) ws[lane] = t;
    }
    __syncthreads();
    float prefix = warp ? ws[warp - 1] : 0.f;
    incl += prefix;
    float w = eff * expf(incl - gv);
    wh[off] = __float2half_rn(w);
}

__global__ void ln_k(const float* __restrict__ x, f16* __restrict__ yh,
                     const float* __restrict__ g, const float* __restrict__ b,
                     int n, int ldx, int ldy)
{
    __shared__ float red[32];
    int row = blockIdx.x;
    const float* xr = x + (long)row * ldx;
    float s = 0.f;
    for (int i = threadIdx.x; i < n; i += blockDim.x) s += xr[i];
    s = blockSum(s, red);
    float mean = s / n;
    float v = 0.f;
    for (int i = threadIdx.x; i < n; i += blockDim.x) {
        float d = xr[i] - mean;
        v += d * d;
    }
    v = blockSum(v, red);
    float rstd = rsqrtf(v / n + 1e-5f);
    for (int i = threadIdx.x; i < n; i += blockDim.x) {
        float val = (xr[i] - mean) * rstd * g[i] + b[i];
        yh[(long)row * ldy + i] = __float2half_rn(val);
    }
}

__global__ void alpha_gate_k(const float* __restrict__ x, const float* __restrict__ Wg,
                             const float* __restrict__ bg, float* __restrict__ alpha)
{
    __shared__ float red[32];
    int row = blockIdx.x;
    const float* xr = x + (long)row * 2 * DF;
    float s = 0.f;
    for (int i = threadIdx.x; i < 2 * DF; i += blockDim.x) s += xr[i] * Wg[i];
    s = blockSum(s, red) + bg[0];
    if (threadIdx.x == 0) alpha[row] *= 1.f / (1.f + expf(-s));
}

// ---------------- host side -------------------------------------------------
static void launch_mma(int epi,
                       const f16* Ah, const f16* Bh,
                       const float* bias, float* C, f16* Ch,
                       int M, int N, int K, int ldab, int ldc,
                       long sA1, long sA2, long sB1, long sB2, long sC1, long sC2,
                       int n1, int n2, int flags)
{
    dim3 grid((M + 127) / 128, (N + 127) / 128, n1 * n2);
    #define MARGS Ah, Bh, bias, C, Ch, M, N, K, ldab, ldc, sA1, sA2, sB1, sB2, sC1, sC2, n2, flags
    switch (epi) {
        case 0: mma_gemm_k<0><<<grid, 256, SMEM_TOT>>>(MARGS); break;
        case 1: mma_gemm_k<1><<<grid, 256, SMEM_TOT>>>(MARGS); break;
        case 3: mma_gemm_k<3><<<grid, 256, SMEM_TOT>>>(MARGS); break;
        case 4: mma_gemm_k<4><<<grid, 256, SMEM_TOT>>>(MARGS); break;
        case 6: mma_gemm_k<6><<<grid, 256, SMEM_TOT>>>(MARGS); break;
        case 7: mma_gemm_k<7><<<grid, 256, SMEM_TOT>>>(MARGS); break;
        case 8: mma_gemm_k<8><<<grid, 256, SMEM_TOT>>>(MARGS); break;
    }
    #undef MARGS
}

static void run_round(const float* x, f16* h, long n) {
    long n8 = n / 8;
    round_k<<<(unsigned)((n8 + 255) / 256), 256>>>((const float4*)x, (uint4*)h, n8);
}

extern "C" void kernel_launch(void* const* d_in, const int* in_sizes, int n_in,
                              void* d_out, int out_size)
{
    const int*   tokens  = (const int*)  d_in[0];
    const float* tok_mu  = (const float*)d_in[1];
    const float* tok_lv  = (const float*)d_in[2];
    const float* tok_ra  = (const float*)d_in[3];
    const float* tok_ft  = (const float*)d_in[4];
    const float* pos_mu  = (const float*)d_in[5];
    const float* log_tau = (const float*)d_in[6];
    const float* Wq      = (const float*)d_in[7];
    const float* bq      = (const float*)d_in[8];
    const float* Whead   = (const float*)d_in[9];
    const float* bhead   = (const float*)d_in[10];
    const float* Wmu     = (const float*)d_in[11];
    const float* bmu     = (const float*)d_in[12];
    const float* Wg      = (const float*)d_in[13];
    const float* bg      = (const float*)d_in[14];
    const float* ln_g    = (const float*)d_in[15];
    const float* ln_b    = (const float*)d_in[16];
    const float* W1      = (const float*)d_in[17];
    const float* b1      = (const float*)d_in[18];
    const float* W2      = (const float*)d_in[19];
    const float* b2      = (const float*)d_in[20];
    const float* lnf_g   = (const float*)d_in[21];
    const float* lnf_b   = (const float*)d_in[22];
    const float* Wlm     = (const float*)d_in[23];
    float* out = (float*)d_out;

    cudaFuncSetAttribute(mma_gemm_k<0>, cudaFuncAttributeMaxDynamicSharedMemorySize, SMEM_TOT);
    cudaFuncSetAttribute(mma_gemm_k<1>, cudaFuncAttributeMaxDynamicSharedMemorySize, SMEM_TOT);
    cudaFuncSetAttribute(mma_gemm_k<3>, cudaFuncAttributeMaxDynamicSharedMemorySize, SMEM_TOT);
    cudaFuncSetAttribute(mma_gemm_k<4>, cudaFuncAttributeMaxDynamicSharedMemorySize, SMEM_TOT);
    cudaFuncSetAttribute(mma_gemm_k<6>, cudaFuncAttributeMaxDynamicSharedMemorySize, SMEM_TOT);
    cudaFuncSetAttribute(mma_gemm_k<7>, cudaFuncAttributeMaxDynamicSharedMemorySize, SMEM_TOT);
    cudaFuncSetAttribute(mma_gemm_k<8>, cudaFuncAttributeMaxDynamicSharedMemorySize, SMEM_TOT);

    float *mu, *iv, *mu2, *alpha, *mahal, *xbuf, *part;
    cudaGetSymbolAddress((void**)&mu,    g_mu);
    cudaGetSymbolAddress((void**)&iv,    g_iv);
    cudaGetSymbolAddress((void**)&mu2,   g_mu2);
    cudaGetSymbolAddress((void**)&alpha, g_alpha);
    cudaGetSymbolAddress((void**)&mahal, g_mahal);
    cudaGetSymbolAddress((void**)&xbuf,  g_xbuf);
    cudaGetSymbolAddress((void**)&part,  g_part);

    f16 *muh, *ivh, *qeh, *wh, *fth, *mhh, *xh, *hh, *h1h;
    f16 *wqh, *whdh, *wmuh, *w1h, *w2h, *wlmh;
    cudaGetSymbolAddress((void**)&muh,  g_muh);
    cudaGetSymbolAddress((void**)&ivh,  g_ivh);
    cudaGetSymbolAddress((void**)&qeh,  g_qeh);
    cudaGetSymbolAddress((void**)&wh,   g_wh);
    cudaGetSymbolAddress((void**)&fth,  g_fth);
    cudaGetSymbolAddress((void**)&mhh,  g_mhh);
    cudaGetSymbolAddress((void**)&xh,   g_xh);
    cudaGetSymbolAddress((void**)&hh,   g_hh);
    cudaGetSymbolAddress((void**)&h1h,  g_h1h);
    cudaGetSymbolAddress((void**)&wqh,  g_wqh);
    cudaGetSymbolAddress((void**)&whdh, g_whdh);
    cudaGetSymbolAddress((void**)&wmuh, g_wmuh);
    cudaGetSymbolAddress((void**)&w1h,  g_w1h);
    cudaGetSymbolAddress((void**)&w2h,  g_w2h);
    cudaGetSymbolAddress((void**)&wlmh, g_wlmh);

    // weight conversions (every call; deterministic)
    run_round(Wq,    wqh,  (long)512 * DS);
    run_round(Whead, whdh, (long)DF * H_ * DF);
    run_round(Wmu,   wmuh, (long)2 * DS * 2 * DF);
    run_round(W1,    w1h,  (long)2 * 4 * DF * 2 * DF);
    run_round(W2,    w2h,  (long)2 * DF * 4 * DF);
    run_round(Wlm,   wlmh, (long)V_ * DF);

    gather_k<<<BL, 256>>>(tokens, tok_mu, tok_lv, tok_ra, tok_ft, pos_mu,
                          mu, iv, alpha, xbuf, xh);

    for (int p = 0; p < 3; p++) {
        prep_k<<<BL, 128>>>(mu, iv, mu2, muh, ivh);

        // q = mu @ Wq^T + bq, packed directly into qe (EPI 7)
        launch_mma(7, muh, wqh, bq, nullptr, qeh,
                   BL, H_ * DS, DS, DS, 0, 0, 0, 0, 0, 0, 0, 1, 1, 0);

        // mahal (without +mu2): tau-damped, causal-N skip
        launch_mma(0, qeh, ivh, nullptr, mahal, nullptr,
                   H_ * L_, L_, 2 * DS, 2 * DS, L_,
                   (long)(H_ * L_) * 2 * DS, 0,
                   (long)L_ * 2 * DS, 0,
                   (long)(H_ * L_) * L_, 0, B_, 1, 1);

        scan_k<<<BHL, 512>>>(mahal, alpha, mu2, log_tau, wh);

        // feats^T
        splitT_k<<<dim3(32, 16, B_), dim3(32, 8)>>>(xbuf, fth);

        // mh = w @ feats^T (causal-K clamp), round-out -> mhh
        launch_mma(8, wh, fth, nullptr, nullptr, mhh,
                   L_, DF, L_, L_, H_ * DF,
                   (long)(H_ * L_) * L_, (long)L_ * L_,
                   (long)DF * L_, 0,
                   (long)L_ * H_ * DF, DF, B_, H_, 2);

        if (p < 2) {
            // meaning = mh @ Whead^T + bhead -> xbuf fp32 AND xh (+DF)
            launch_mma(6, mhh, whdh, bhead, xbuf + DF, xh + DF,
                       BL, DF, H_ * DF, H_ * DF, 2 * DF,
                       0, 0, 0, 0, 0, 0, 1, 1, 0);

            alpha_gate_k<<<BL, 256>>>(xbuf, Wg + p * 2 * DF, bg + p, alpha);

            // mu-update split-K: partials = x @ Wmu[p]^T (4 K-chunks of 512)
            launch_mma(0, xh, wmuh + (long)p * DS * 2 * DF,
                       nullptr, part, nullptr,
                       BL, DS, 512, 2 * DF, DS,
                       0, 512, 0, 512, 0, (long)BL * DS, 1, 4, 4);
            mu_red_k<<<BL * DS / 256, 256>>>(part, bmu + p * DS, mu);

            // h = LN(x)
            ln_k<<<BL, 256>>>(xbuf, hh, ln_g + p * 2 * DF, ln_b + p * 2 * DF,
                              2 * DF, 2 * DF, 2 * DF);

            // h1 = gelu(h @ W1[p]^T + b1[p]) round-out
            launch_mma(3, hh, w1h + (long)p * 4 * DF * 2 * DF,
                       b1 + p * 4 * DF, nullptr, h1h,
                       BL, 4 * DF, 2 * DF, 2 * DF, 4 * DF,
                       0, 0, 0, 0, 0, 0, 1, 1, 0);

            // feats += h1 @ W2[p]^T + b2[p] : fp32 AND round into xh
            launch_mma(4, h1h, w2h + (long)p * DF * 4 * DF,
                       b2 + p * DF, xbuf, xh,
                       BL, DF, 4 * DF, 4 * DF, 2 * DF,
                       0, 0, 0, 0, 0, 0, 1, 1, 0);
        } else {
            // final-pass meaning: feeds only LN+LM head -> fp32 only
            launch_mma(1, mhh, whdh, bhead, xbuf + DF, nullptr,
                       BL, DF, H_ * DF, H_ * DF, 2 * DF,
                       0, 0, 0, 0, 0, 0, 1, 1, 0);
        }
    }

    // y = LN(meaning); logits = y @ Wlm^T
    ln_k<<<BL, 256>>>(xbuf + DF, hh, lnf_g, lnf_b, DF, 2 * DF, DF);
    launch_mma(0, hh, wlmh, nullptr, out, nullptr,
               BL, V_, DF, DF, V_, 0, 0, 0, 0, 0, 0, 1, 1, 0);
}

// round 17
// speedup vs baseline: 1.5465x; 1.0232x over previous
#include <cuda_runtime.h>
#include <cuda_fp16.h>
#include <math.h>
#include <stdint.h>

#define B_  4
#define L_  512
#define DS  128
#define DF  1000
#define H_  4
#define V_  32000
#define BL  2048    /* B*L   */
#define BHL 8192    /* B*H*L */

typedef __half f16;

// ---------------- fp32 scratch -------------------------------------------
__device__ float g_mu   [BL * DS];
__device__ float g_iv   [BL * DS];
__device__ float g_mu2  [BL];
__device__ float g_alpha[BL];
__device__ float g_xbuf [(size_t)BL * 2 * DF];
__device__ float g_part [4 * BL * DS];          // split-K partials for mu GEMM

// ---------------- fp16 scratch (all single-rounded) -------------------------
__device__ f16 g_muh[BL * DS];
__device__ f16 g_ivh[BL * 2 * DS];
__device__ f16 g_qeh[BHL * 2 * DS];
__device__ f16 g_mahalh[(size_t)BHL * L_];
__device__ f16 g_wh [(size_t)BHL * L_];
__device__ f16 g_fth[(size_t)B_ * DF * L_];
__device__ f16 g_mhh[(size_t)BL * H_ * DF];
__device__ f16 g_xh [(size_t)BL * 2 * DF];
__device__ f16 g_hh [(size_t)BL * 2 * DF];
__device__ f16 g_h1h[(size_t)BL * 4 * DF];
// weights
__device__ f16 g_wqh[512 * DS];
__device__ f16 g_whdh[(size_t)DF * H_ * DF];
__device__ f16 g_wmuh[(size_t)2 * DS * 2 * DF];
__device__ f16 g_w1h[(size_t)2 * 4 * DF * 2 * DF];
__device__ f16 g_w2h[(size_t)2 * DF * 4 * DF];
__device__ f16 g_wlmh[(size_t)V_ * DF];

// ---------------- helpers --------------------------------------------------
__device__ __forceinline__ float warpSum(float v) {
    #pragma unroll
    for (int o = 16; o > 0; o >>= 1) v += __shfl_down_sync(0xffffffffu, v, o);
    return v;
}
__device__ float blockSum(float v, float* red) {
    int lane = threadIdx.x & 31, w = threadIdx.x >> 5;
    v = warpSum(v);
    __syncthreads();
    if (lane == 0) red[w] = v;
    __syncthreads();
    if (w == 0) {
        int nw = (blockDim.x + 31) >> 5;
        float t = (lane < nw) ? red[lane] : 0.f;
        t = warpSum(t);
        if (lane == 0) red[0] = t;
    }
    __syncthreads();
    return red[0];
}

// ---------------- mma.sync GEMM engine -------------------------------------
__device__ __forceinline__ void ldsm4(uint32_t& r0, uint32_t& r1, uint32_t& r2,
                                      uint32_t& r3, uint32_t a) {
    asm volatile("ldmatrix.sync.aligned.m8n8.x4.shared.b16 {%0,%1,%2,%3}, [%4];"
                 : "=r"(r0), "=r"(r1), "=r"(r2), "=r"(r3) : "r"(a));
}
__device__ __forceinline__ void mma_f16(float* c, const uint32_t* a,
                                        uint32_t b0, uint32_t b1) {
    asm volatile(
        "mma.sync.aligned.m16n8k16.row.col.f32.f16.f16.f32 "
        "{%0,%1,%2,%3}, {%4,%5,%6,%7}, {%8,%9}, {%0,%1,%2,%3};"
        : "+f"(c[0]), "+f"(c[1]), "+f"(c[2]), "+f"(c[3])
        : "r"(a[0]), "r"(a[1]), "r"(a[2]), "r"(a[3]), "r"(b0), "r"(b1));
}
__device__ __forceinline__ void cpa16(uint32_t dst, const void* src, bool p) {
    asm volatile("cp.async.cg.shared.global [%0], [%1], 16, %2;"
                 :: "r"(dst), "l"(src), "r"(p ? 16 : 0));
}
__device__ __forceinline__ void cpa_commit() {
    asm volatile("cp.async.commit_group;");
}
template<int NN>
__device__ __forceinline__ void cpa_wait() {
    asm volatile("cp.async.wait_group %0;" :: "n"(NN));
}

// EPI: 0 C=v; 1 C=v+bias; 3 Ch=round(gelu(v+bias));
//      4 Cf=C+v+bias fp32, Ch=round(Cf); 6 C=v+bias fp32, Ch=round;
//      7 qe-pack round; 8 Ch=round(v)
template<int EPI>
__device__ __forceinline__ void epi_store(float v, int r, int c, int M, int N,
                                          int ldc, const float* bias, float* C,
                                          f16* Ch) {
    if (r >= M || c >= N) return;
    if (EPI == 1 || EPI == 3 || EPI == 4 || EPI == 6 || EPI == 7) v += bias[c];
    if (EPI == 7) {
        int b = r >> 9, l = r & (L_ - 1), h = c >> 7, d = c & 127;
        long orow = ((long)b * (H_ * L_) + h * L_ + l) * (2 * DS);
        Ch[orow + d]      = __float2half_rn(v * v);
        Ch[orow + DS + d] = __float2half_rn(-2.f * v);
        return;
    }
    long off = (long)r * ldc + c;
    if (EPI == 0 || EPI == 1) C[off] = v;
    else if (EPI == 3) {
        v = 0.5f * v * (1.0f + erff(v * 0.7071067811865476f));
        Ch[off] = __float2half_rn(v);
    } else if (EPI == 4) {
        float nv = C[off] + v;
        C[off] = nv;
        Ch[off] = __float2half_rn(nv);
    } else if (EPI == 6) {
        C[off] = v;
        Ch[off] = __float2half_rn(v);
    } else if (EPI == 8) {
        Ch[off] = __float2half_rn(v);
    }
}

// vectorized fp32 pair store (EPI 0/1). Requires N even (all callers).
template<int EPI>
__device__ __forceinline__ void epi_store_f2(float v0, float v1, int r, int c,
                                             int M, int N, int ldc,
                                             const float* bias, float* C) {
    if (r >= M || c >= N) return;
    if (EPI == 1) { v0 += bias[c]; v1 += bias[c + 1]; }
    *(float2*)(&C[(long)r * ldc + c]) = make_float2(v0, v1);
}

#define KT         64
#define SMEM_STAGE 32768      /* A 16K | B 16K  (1-term layout) */
#define SMEM_TOT   (3 * SMEM_STAGE)   /* 96 KB -> 2 CTAs/SM */

// flags: bit0 = causal N-tile skip (period 512); bit1 = causal K clamp;
//        bit2 = split-K chunk clamp. All GEMMs 1-term (A hi x B hi).
template<int EPI>
__global__ void __launch_bounds__(256, 2) mma_gemm_k(
    const f16* __restrict__ Ah, const f16* __restrict__ Bh,
    const float* __restrict__ bias, float* __restrict__ C,
    f16* __restrict__ Ch,
    int M, int N, int K, int ldab, int ldc,
    long sA1, long sA2, long sB1, long sB2, long sC1, long sC2, int n2,
    int flags)
{
    extern __shared__ __align__(16) unsigned char smem_raw[];
    const uint32_t sbase = (uint32_t)__cvta_generic_to_shared(smem_raw);

    const int bm = blockIdx.x * 128;   // M fast -> better L2 reuse of B stripes
    const int bn = blockIdx.y * 128;

    if ((flags & 1) && bn >= (bm & 511) + 128) return;   // causal skip
    if (flags & 2) { int ke = (bm & 511) + 128; if (ke < K) K = ke; }

    int z  = blockIdx.z;
    int z1 = z / n2, z2 = z - z1 * n2;
    if (flags & 4) { int rem = ldab - z2 * K; if (rem < K) K = rem; }
    Ah += (long)z1 * sA1 + (long)z2 * sA2;
    Bh += (long)z1 * sB1 + (long)z2 * sB2;
    long coff = (long)z1 * sC1 + (long)z2 * sC2;
    if (C)  C  += coff;
    if (Ch) Ch += coff;

    const int tid  = threadIdx.x;
    const int lane = tid & 31;
    const int warp = tid >> 5;
    const int wm = warp >> 2;      // 0..1
    const int wn = warp & 3;       // 0..3
    const int kso = wm << 1;       // ks phase skew across SMSP-paired warps

    float acc[4][4][4];
    #pragma unroll
    for (int i = 0; i < 4; i++)
        #pragma unroll
        for (int j = 0; j < 4; j++)
            #pragma unroll
            for (int e = 0; e < 4; e++) acc[i][j][e] = 0.f;

    const int T = (K + KT - 1) / KT;

    auto load_stage = [&](int st, int kt) {
        const uint32_t sb = sbase + st * SMEM_STAGE;
        const int k0 = kt * KT;
        #pragma unroll
        for (int it = 0; it < 4; it++) {
            int cch = tid + it * 256;            // 0..1023
            int row = cch >> 3, u = cch & 7;
            int gk = k0 + u * 8;
            bool kok = gk < K;
            int gkc = kok ? gk : 0;
            uint32_t sw = row * 128 + ((u ^ (row & 7)) << 4);
            {   // A
                int gm = bm + row;
                bool p = kok && (gm < M);
                long off = (long)(p ? gm : 0) * ldab + gkc;
                cpa16(sb + sw, Ah + off, p);
            }
            {   // B
                int gn = bn + row;
                bool p = kok && (gn < N);
                long off = (long)(p ? gn : 0) * ldab + gkc;
                cpa16(sb + 16384 + sw, Bh + off, p);
            }
        }
    };

    // prologue: stages 0 and 1
    load_stage(0, 0);
    cpa_commit();
    if (1 < T) load_stage(1, 1);
    cpa_commit();

    for (int t = 0; t < T; t++) {
        cpa_wait<1>();
        __syncthreads();

        if (t + 2 < T) load_stage((t + 2) % 3, t + 2);
        cpa_commit();                         // unconditional: keeps group math exact

        const uint32_t sb  = sbase + (t % 3) * SMEM_STAGE;
        const uint32_t sAh = sb, sBh = sb + 16384;

        #pragma unroll
        for (int ksi = 0; ksi < 4; ksi++) {
            const int ks = (ksi + kso) & 3;
            const int kb = ks * 16;
            uint32_t bhf[8];
            #pragma unroll
            for (int p2 = 0; p2 < 2; p2++) {
                int n_ = wn * 32 + p2 * 16 + (lane & 7) + ((lane >> 4) << 3);
                int kc = kb + (((lane >> 3) & 1) << 3);
                uint32_t off = n_ * 128 + ((((kc >> 3) ^ (n_ & 7))) << 4);
                ldsm4(bhf[p2*4+0], bhf[p2*4+1], bhf[p2*4+2], bhf[p2*4+3], sBh + off);
            }
            #pragma unroll
            for (int i = 0; i < 4; i++) {
                int r_ = wm * 64 + i * 16 + (lane & 7) + (((lane >> 3) & 1) << 3);
                int kc = kb + ((lane >> 4) << 3);
                uint32_t off = r_ * 128 + ((((kc >> 3) ^ (r_ & 7))) << 4);
                uint32_t ahf[4];
                ldsm4(ahf[0], ahf[1], ahf[2], ahf[3], sAh + off);
                #pragma unroll
                for (int j = 0; j < 4; j++) {
                    int bi = (j >> 1) * 4 + (j & 1) * 2;
                    mma_f16(acc[i][j], ahf, bhf[bi], bhf[bi+1]);
                }
            }
        }
        __syncthreads();
    }

    // ---- epilogue ----
    #pragma unroll
    for (int i = 0; i < 4; i++) {
        int r0 = bm + wm * 64 + i * 16 + (lane >> 2);
        #pragma unroll
        for (int j = 0; j < 4; j++) {
            int c0 = bn + wn * 32 + j * 8 + ((lane & 3) << 1);
            if (EPI == 0 || EPI == 1) {
                epi_store_f2<EPI>(acc[i][j][0], acc[i][j][1], r0,     c0, M, N, ldc, bias, C);
                epi_store_f2<EPI>(acc[i][j][2], acc[i][j][3], r0 + 8, c0, M, N, ldc, bias, C);
            } else {
                epi_store<EPI>(acc[i][j][0], r0,     c0,     M, N, ldc, bias, C, Ch);
                epi_store<EPI>(acc[i][j][1], r0,     c0 + 1, M, N, ldc, bias, C, Ch);
                epi_store<EPI>(acc[i][j][2], r0 + 8, c0,     M, N, ldc, bias, C, Ch);
                epi_store<EPI>(acc[i][j][3], r0 + 8, c0 + 1, M, N, ldc, bias, C, Ch);
            }
        }
    }
}

// ---------------- round / transpose kernels ---------------------------------
__global__ void round_k(const float4* __restrict__ x, uint4* __restrict__ h,
                        long n8)
{
    long i = (long)blockIdx.x * 256 + threadIdx.x;
    if (i >= n8) return;
    float4 a = x[2 * i], b = x[2 * i + 1];
    float vs[8] = {a.x, a.y, a.z, a.w, b.x, b.y, b.z, b.w};
    f16 hv[8];
    #pragma unroll
    for (int j = 0; j < 8; j++) hv[j] = __float2half_rn(vs[j]);
    h[i] = *(uint4*)hv;
}

// feats [b, l, :DF] (ld 2DF) -> out [b, f, l]
__global__ void splitT_k(const float* __restrict__ x, f16* __restrict__ oh)
{
    __shared__ float t[32][33];
    int b  = blockIdx.z;
    int j0 = blockIdx.y * 32;
    int f0 = blockIdx.x * 32;
    const float* xb = x + (long)b * L_ * 2 * DF;
    int tx = threadIdx.x, ty = threadIdx.y;
    #pragma unroll
    for (int s = 0; s < 32; s += 8) {
        int j = j0 + ty + s, f = f0 + tx;
        t[ty + s][tx] = (f < DF) ? xb[(long)j * 2 * DF + f] : 0.f;
    }
    __syncthreads();
    #pragma unroll
    for (int s = 0; s < 32; s += 8) {
        int f = f0 + ty + s, j = j0 + tx;
        if (f < DF) {
            long o = ((long)b * DF + f) * L_ + j;
            oh[o] = __float2half_rn(t[tx][ty + s]);
        }
    }
}

// ---------------- model-specific small kernels -----------------------------
// gather + fused prep (mu2/muh/ivh)
__global__ void gather_k(const int* __restrict__ tokens,
                         const float* __restrict__ tok_mu,
                         const float* __restrict__ tok_lv,
                         const float* __restrict__ tok_ra,
                         const float* __restrict__ tok_ft,
                         const float* __restrict__ pos_mu,
                         float* __restrict__ mu, float* __restrict__ iv,
                         float* __restrict__ mu2, float* __restrict__ alpha,
                         float* __restrict__ xbuf, f16* __restrict__ xh,
                         f16* __restrict__ muh, f16* __restrict__ ivh)
{
    int row = blockIdx.x;
    int l   = row & (L_ - 1);
    int tok = tokens[row];
    int tid = threadIdx.x;            // 256
    __shared__ float sm[4];
    if (tid < DS) {
        int d = tid;
        float m = tok_mu[(long)tok * DS + d] + pos_mu[l * DS + d];
        float v = expf(-tok_lv[(long)tok * DS + d]);
        float miv = m * v;
        mu[row * DS + d] = m;
        iv[row * DS + d] = v;
        muh[row * DS + d]          = __float2half_rn(m);
        ivh[row * 2 * DS + d]      = __float2half_rn(v);
        ivh[row * 2 * DS + DS + d] = __float2half_rn(miv);
        float s = warpSum(m * miv);
        if ((d & 31) == 0) sm[d >> 5] = s;
    }
    if (tid == 0)
        alpha[row] = 1.f / (1.f + expf(-tok_ra[tok]));
    __syncthreads();
    if (tid == 0) mu2[row] = sm[0] + sm[1] + sm[2] + sm[3];
    for (int f = tid; f < DF; f += blockDim.x) {
        float v = tok_ft[(long)tok * DF + f];
        long o = (long)row * 2 * DF + f;
        xbuf[o] = v;
        xh[o] = __float2half_rn(v);
    }
}

// mu += tanh(sum of 4 split-K partials + bias), fused next-pass prep
__global__ void mu_red_k(const float* __restrict__ part,
                         const float* __restrict__ bmu, float* __restrict__ mu,
                         const float* __restrict__ iv, float* __restrict__ mu2,
                         f16* __restrict__ muh, f16* __restrict__ ivh)
{
    int row = blockIdx.x;             // BL blocks x 128 threads
    int d   = threadIdx.x;
    int i   = row * DS + d;
    float s = part[i] + part[i + BL * DS] + part[i + 2 * BL * DS]
            + part[i + 3 * BL * DS] + bmu[d];
    float m = mu[i] + tanhf(s);
    mu[i] = m;
    float v = iv[i];
    float miv = m * v;
    muh[i] = __float2half_rn(m);
    ivh[row * 2 * DS + DS + d] = __float2half_rn(miv);  // iv half is static
    float r = warpSum(m * miv);
    __shared__ float sm[4];
    if ((d & 31) == 0) sm[d >> 5] = r;
    __syncthreads();
    if (d == 0) mu2[row] = sm[0] + sm[1] + sm[2] + sm[3];
}

__global__ void __launch_bounds__(512) scan_k(const f16* __restrict__ mahalh,
                                              const float* __restrict__ alpha,
                                              const float* __restrict__ mu2,
                                              const float* __restrict__ log_tau,
                                              f16* __restrict__ wh)
{
    int row = blockIdx.x;
    int b = row >> 11;
    int l = row & (L_ - 1);
    int j = threadIdx.x;
    float tau = expf(log_tau[0]);
    long off = (long)row * L_ + j;
    float eff = 0.f;
    if (j <= l) {
        float m  = __half2float(mahalh[off]) + mu2[b * L_ + j];
        float Kv = expf(-0.5f * m / tau);
        eff = fminf(alpha[b * L_ + j] * Kv, 1.f - 1e-6f);
    }
    float gv = log1pf(-eff);

    int lane = j & 31, warp = j >> 5;
    float incl = gv;
    #pragma unroll
    for (int o = 1; o < 32; o <<= 1) {
        float t = __shfl_up_sync(0xffffffffu, incl, o);
        if (lane >= o) incl += t;
    }
    __shared__ float ws[16];
    if (lane == 31) ws[warp] = incl;
    __syncthreads();
    if (warp == 0) {
        float t = (lane < 16) ? ws[lane] : 0.f;
        #pragma unroll
        for (int o = 1; o < 16; o <<= 1) {
            float u = __shfl_up_sync(0xffffffffu, t, o);
            if (lane >= o) t += u;
        }
        if (lane < 16) ws[lane] = t;
    }
    __syncthreads();
    float prefix = warp ? ws[warp - 1] : 0.f;
    incl += prefix;
    float w = eff * expf(incl - gv);
    wh[off] = __float2half_rn(w);
}

__global__ void ln_k(const float* __restrict__ x, f16* __restrict__ yh,
                     const float* __restrict__ g, const float* __restrict__ b,
                     int n, int ldx, int ldy)
{
    __shared__ float red[32];
    int row = blockIdx.x;
    const float* xr = x + (long)row * ldx;
    float s = 0.f;
    for (int i = threadIdx.x; i < n; i += blockDim.x) s += xr[i];
    s = blockSum(s, red);
    float mean = s / n;
    float v = 0.f;
    for (int i = threadIdx.x; i < n; i += blockDim.x) {
        float d = xr[i] - mean;
        v += d * d;
    }
    v = blockSum(v, red);
    float rstd = rsqrtf(v / n + 1e-5f);
    for (int i = threadIdx.x; i < n; i += blockDim.x) {
        float val = (xr[i] - mean) * rstd * g[i] + b[i];
        yh[(long)row * ldy + i] = __float2half_rn(val);
    }
}

__global__ void alpha_gate_k(const float* __restrict__ x, const float* __restrict__ Wg,
                             const float* __restrict__ bg, float* __restrict__ alpha)
{
    __shared__ float red[32];
    int row = blockIdx.x;
    const float* xr = x + (long)row * 2 * DF;
    float s = 0.f;
    for (int i = threadIdx.x; i < 2 * DF; i += blockDim.x) s += xr[i] * Wg[i];
    s = blockSum(s, red) + bg[0];
    if (threadIdx.x == 0) alpha[row] *= 1.f / (1.f + expf(-s));
}

// ---------------- host side -------------------------------------------------
static void launch_mma(int epi,
                       const f16* Ah, const f16* Bh,
                       const float* bias, float* C, f16* Ch,
                       int M, int N, int K, int ldab, int ldc,
                       long sA1, long sA2, long sB1, long sB2, long sC1, long sC2,
                       int n1, int n2, int flags)
{
    dim3 grid((M + 127) / 128, (N + 127) / 128, n1 * n2);
    #define MARGS Ah, Bh, bias, C, Ch, M, N, K, ldab, ldc, sA1, sA2, sB1, sB2, sC1, sC2, n2, flags
    switch (epi) {
        case 0: mma_gemm_k<0><<<grid, 256, SMEM_TOT>>>(MARGS); break;
        case 1: mma_gemm_k<1><<<grid, 256, SMEM_TOT>>>(MARGS); break;
        case 3: mma_gemm_k<3><<<grid, 256, SMEM_TOT>>>(MARGS); break;
        case 4: mma_gemm_k<4><<<grid, 256, SMEM_TOT>>>(MARGS); break;
        case 6: mma_gemm_k<6><<<grid, 256, SMEM_TOT>>>(MARGS); break;
        case 7: mma_gemm_k<7><<<grid, 256, SMEM_TOT>>>(MARGS); break;
        case 8: mma_gemm_k<8><<<grid, 256, SMEM_TOT>>>(MARGS); break;
    }
    #undef MARGS
}

static void run_round(const float* x, f16* h, long n) {
    long n8 = n / 8;
    round_k<<<(unsigned)((n8 + 255) / 256), 256>>>((const float4*)x, (uint4*)h, n8);
}

extern "C" void kernel_launch(void* const* d_in, const int* in_sizes, int n_in,
                              void* d_out, int out_size)
{
    const int*   tokens  = (const int*)  d_in[0];
    const float* tok_mu  = (const float*)d_in[1];
    const float* tok_lv  = (const float*)d_in[2];
    const float* tok_ra  = (const float*)d_in[3];
    const float* tok_ft  = (const float*)d_in[4];
    const float* pos_mu  = (const float*)d_in[5];
    const float* log_tau = (const float*)d_in[6];
    const float* Wq      = (const float*)d_in[7];
    const float* bq      = (const float*)d_in[8];
    const float* Whead   = (const float*)d_in[9];
    const float* bhead   = (const float*)d_in[10];
    const float* Wmu     = (const float*)d_in[11];
    const float* bmu     = (const float*)d_in[12];
    const float* Wg      = (const float*)d_in[13];
    const float* bg      = (const float*)d_in[14];
    const float* ln_g    = (const float*)d_in[15];
    const float* ln_b    = (const float*)d_in[16];
    const float* W1      = (const float*)d_in[17];
    const float* b1      = (const float*)d_in[18];
    const float* W2      = (const float*)d_in[19];
    const float* b2      = (const float*)d_in[20];
    const float* lnf_g   = (const float*)d_in[21];
    const float* lnf_b   = (const float*)d_in[22];
    const float* Wlm     = (const float*)d_in[23];
    float* out = (float*)d_out;

    cudaFuncSetAttribute(mma_gemm_k<0>, cudaFuncAttributeMaxDynamicSharedMemorySize, SMEM_TOT);
    cudaFuncSetAttribute(mma_gemm_k<1>, cudaFuncAttributeMaxDynamicSharedMemorySize, SMEM_TOT);
    cudaFuncSetAttribute(mma_gemm_k<3>, cudaFuncAttributeMaxDynamicSharedMemorySize, SMEM_TOT);
    cudaFuncSetAttribute(mma_gemm_k<4>, cudaFuncAttributeMaxDynamicSharedMemorySize, SMEM_TOT);
    cudaFuncSetAttribute(mma_gemm_k<6>, cudaFuncAttributeMaxDynamicSharedMemorySize, SMEM_TOT);
    cudaFuncSetAttribute(mma_gemm_k<7>, cudaFuncAttributeMaxDynamicSharedMemorySize, SMEM_TOT);
    cudaFuncSetAttribute(mma_gemm_k<8>, cudaFuncAttributeMaxDynamicSharedMemorySize, SMEM_TOT);

    float *mu, *iv, *mu2, *alpha, *xbuf, *part;
    cudaGetSymbolAddress((void**)&mu,    g_mu);
    cudaGetSymbolAddress((void**)&iv,    g_iv);
    cudaGetSymbolAddress((void**)&mu2,   g_mu2);
    cudaGetSymbolAddress((void**)&alpha, g_alpha);
    cudaGetSymbolAddress((void**)&xbuf,  g_xbuf);
    cudaGetSymbolAddress((void**)&part,  g_part);

    f16 *muh, *ivh, *qeh, *mahalh, *wh, *fth, *mhh, *xh, *hh, *h1h;
    f16 *wqh, *whdh, *wmuh, *w1h, *w2h, *wlmh;
    cudaGetSymbolAddress((void**)&muh,    g_muh);
    cudaGetSymbolAddress((void**)&ivh,    g_ivh);
    cudaGetSymbolAddress((void**)&qeh,    g_qeh);
    cudaGetSymbolAddress((void**)&mahalh, g_mahalh);
    cudaGetSymbolAddress((void**)&wh,     g_wh);
    cudaGetSymbolAddress((void**)&fth,    g_fth);
    cudaGetSymbolAddress((void**)&mhh,    g_mhh);
    cudaGetSymbolAddress((void**)&xh,     g_xh);
    cudaGetSymbolAddress((void**)&hh,     g_hh);
    cudaGetSymbolAddress((void**)&h1h,    g_h1h);
    cudaGetSymbolAddress((void**)&wqh,    g_wqh);
    cudaGetSymbolAddress((void**)&whdh,   g_whdh);
    cudaGetSymbolAddress((void**)&wmuh,   g_wmuh);
    cudaGetSymbolAddress((void**)&w1h,    g_w1h);
    cudaGetSymbolAddress((void**)&w2h,    g_w2h);
    cudaGetSymbolAddress((void**)&wlmh,   g_wlmh);

    // weight conversions (every call; deterministic)
    run_round(Wq,    wqh,  (long)512 * DS);
    run_round(Whead, whdh, (long)DF * H_ * DF);
    run_round(Wmu,   wmuh, (long)2 * DS * 2 * DF);
    run_round(W1,    w1h,  (long)2 * 4 * DF * 2 * DF);
    run_round(W2,    w2h,  (long)2 * DF * 4 * DF);
    run_round(Wlm,   wlmh, (long)V_ * DF);

    gather_k<<<BL, 256>>>(tokens, tok_mu, tok_lv, tok_ra, tok_ft, pos_mu,
                          mu, iv, mu2, alpha, xbuf, xh, muh, ivh);

    for (int p = 0; p < 3; p++) {
        // q = mu @ Wq^T + bq, packed directly into qe (EPI 7)
        launch_mma(7, muh, wqh, bq, nullptr, qeh,
                   BL, H_ * DS, DS, DS, 0, 0, 0, 0, 0, 0, 0, 1, 1, 0);

        // mahal (without +mu2): tau-damped, causal-N skip, f16 out
        launch_mma(8, qeh, ivh, nullptr, nullptr, mahalh,
                   H_ * L_, L_, 2 * DS, 2 * DS, L_,
                   (long)(H_ * L_) * 2 * DS, 0,
                   (long)L_ * 2 * DS, 0,
                   (long)(H_ * L_) * L_, 0, B_, 1, 1);

        scan_k<<<BHL, 512>>>(mahalh, alpha, mu2, log_tau, wh);

        // feats^T
        splitT_k<<<dim3(32, 16, B_), dim3(32, 8)>>>(xbuf, fth);

        // mh = w @ feats^T (causal-K clamp), round-out -> mhh
        launch_mma(8, wh, fth, nullptr, nullptr, mhh,
                   L_, DF, L_, L_, H_ * DF,
                   (long)(H_ * L_) * L_, (long)L_ * L_,
                   (long)DF * L_, 0,
                   (long)L_ * H_ * DF, DF, B_, H_, 2);

        if (p < 2) {
            // meaning = mh @ Whead^T + bhead -> xbuf fp32 AND xh (+DF)
            launch_mma(6, mhh, whdh, bhead, xbuf + DF, xh + DF,
                       BL, DF, H_ * DF, H_ * DF, 2 * DF,
                       0, 0, 0, 0, 0, 0, 1, 1, 0);

            alpha_gate_k<<<BL, 256>>>(xbuf, Wg + p * 2 * DF, bg + p, alpha);

            // mu-update split-K: partials = x @ Wmu[p]^T (4 K-chunks of 512)
            launch_mma(0, xh, wmuh + (long)p * DS * 2 * DF,
                       nullptr, part, nullptr,
                       BL, DS, 512, 2 * DF, DS,
                       0, 512, 0, 512, 0, (long)BL * DS, 1, 4, 4);
            // fused: mu update + next-pass muh / mu*iv / mu2
            mu_red_k<<<BL, 128>>>(part, bmu + p * DS, mu, iv, mu2, muh, ivh);

            // h = LN(x)
            ln_k<<<BL, 256>>>(xbuf, hh, ln_g + p * 2 * DF, ln_b + p * 2 * DF,
                              2 * DF, 2 * DF, 2 * DF);

            // h1 = gelu(h @ W1[p]^T + b1[p]) round-out
            launch_mma(3, hh, w1h + (long)p * 4 * DF * 2 * DF,
                       b1 + p * 4 * DF, nullptr, h1h,
                       BL, 4 * DF, 2 * DF, 2 * DF, 4 * DF,
                       0, 0, 0, 0, 0, 0, 1, 1, 0);

            // feats += h1 @ W2[p]^T + b2[p] : fp32 AND round into xh
            launch_mma(4, h1h, w2h + (long)p * DF * 4 * DF,
                       b2 + p * DF, xbuf, xh,
                       BL, DF, 4 * DF, 4 * DF, 2 * DF,
                       0, 0, 0, 0, 0, 0, 1, 1, 0);
        } else {
            // final-pass meaning: feeds only LN+LM head -> fp32 only
            launch_mma(1, mhh, whdh, bhead, xbuf + DF, nullptr,
                       BL, DF, H_ * DF, H_ * DF, 2 * DF,
                       0, 0, 0, 0, 0, 0, 1, 1, 0);
        }
    }

    // y = LN(meaning); logits = y @ Wlm^T
    ln_k<<<BL, 256>>>(xbuf + DF, hh, lnf_g, lnf_b, DF, 2 * DF, DF);
    launch_mma(0, hh, wlmh, nullptr, out, nullptr,
               BL, V_, DF, DF, V_, 0, 0, 0, 0, 0, 0, 1, 1, 0);
}